// round 8
// baseline (speedup 1.0000x reference)
#include <cuda_runtime.h>
#include <cuda_bf16.h>
#include <cuda_fp16.h>
#include <cstdint>

#define NM   8192
#define DIMM 256
#define NH   8
#define EE   32
#define MB   16
#define NB   512
#define NKEY 32
#define NQKV 768

// ---------------- scratch ----------------------------------------------------
__device__ float g_xp[NM * DIMM];                         // fp32 PE'd x
__device__ __align__(16) __nv_bfloat16 g_xph[NM * DIMM];  // bf16 splits of xp
__device__ __align__(16) __nv_bfloat16 g_xpl[NM * DIMM];
__device__ float g_wqk[512 * DIMM];                       // permuted fp32 Q,K weights
__device__ __align__(16) __nv_bfloat16 g_wvh[256 * DIMM]; // permuted V weight splits
__device__ __align__(16) __nv_bfloat16 g_wvl[256 * DIMM];
__device__ __align__(16) __nv_bfloat16 g_wph[DIMM * DIMM];
__device__ __align__(16) __nv_bfloat16 g_wpl[DIMM * DIMM];
__device__ __align__(16) __nv_bfloat16 g_aoh[NM * DIMM];
__device__ __align__(16) __nv_bfloat16 g_aol[NM * DIMM];
__device__ float g_q[NH * NM * EE];
__device__ float g_k[NH * NM * EE];
__device__ __align__(16) __half g_vh[NH * NM * EE];       // V in fp16
__device__ float g_kmean[NH * NB * EE];
__device__ int   g_idx[NH * NM * 2];

// ---------------- packed f32x2 helpers ----------------------------------------
typedef unsigned long long ull;
__device__ __forceinline__ ull pack2(float x, float y) {
    ull r; asm("mov.b64 %0, {%1, %2};" : "=l"(r) : "f"(x), "f"(y)); return r;
}
__device__ __forceinline__ ull fma2(ull a, ull b, ull c) {
    ull d; asm("fma.rn.f32x2 %0, %1, %2, %3;" : "=l"(d) : "l"(a), "l"(b), "l"(c));
    return d;
}
__device__ __forceinline__ void unpack2(ull v, float& lo, float& hi) {
    asm("mov.b64 {%0, %1}, %2;" : "=f"(lo), "=f"(hi) : "l"(v));
}

// ---------------- mma.sync helpers ---------------------------------------------
__device__ __forceinline__ uint32_t smem_u32(const void* p) {
    uint32_t a;
    asm("{ .reg .u64 t; cvta.to.shared.u64 t, %1; cvt.u32.u64 %0, t; }" : "=r"(a) : "l"(p));
    return a;
}
__device__ __forceinline__ uint32_t swz_addr(uint32_t base, int r, int cb) {
    uint32_t off = (uint32_t)(r * 128 + cb);
    off ^= (off >> 3) & 0x70;
    return base + off;
}
__device__ __forceinline__ void ldsm4(uint32_t& r0, uint32_t& r1, uint32_t& r2,
                                      uint32_t& r3, uint32_t addr) {
    asm volatile("ldmatrix.sync.aligned.m8n8.x4.shared.b16 {%0,%1,%2,%3}, [%4];"
                 : "=r"(r0), "=r"(r1), "=r"(r2), "=r"(r3) : "r"(addr));
}
__device__ __forceinline__ void mma16816(float* d, const uint32_t* a,
                                         uint32_t b0, uint32_t b1) {
    asm volatile(
        "mma.sync.aligned.m16n8k16.row.col.f32.bf16.bf16.f32 "
        "{%0,%1,%2,%3}, {%4,%5,%6,%7}, {%8,%9}, {%0,%1,%2,%3};"
        : "+f"(d[0]), "+f"(d[1]), "+f"(d[2]), "+f"(d[3])
        : "r"(a[0]), "r"(a[1]), "r"(a[2]), "r"(a[3]), "r"(b0), "r"(b1));
}
__device__ __forceinline__ void cpasync16(uint32_t dst, const void* src) {
    asm volatile("cp.async.cg.shared.global [%0], [%1], 16;" :: "r"(dst), "l"(src));
}

// ---------------- k0: weight permutation + splits --------------------------------
__global__ void kconv_w(const float* __restrict__ Wq, const float* __restrict__ Wp) {
    int i = blockIdx.x * 256 + threadIdx.x;    // 1024 blocks
    if (i < NQKV * DIMM) {
        int c = i >> 8, d = i & 255;
        int h = c / 96, t = c % 96, e = t / 3, s = t - e * 3;
        float v = Wq[i];
        if (s < 2) {
            g_wqk[(h * 64 + e * 2 + s) * DIMM + d] = v;
        } else {
            __nv_bfloat16 hh = __float2bfloat16(v);
            int idx = (h * 32 + e) * DIMM + d;
            g_wvh[idx] = hh;
            g_wvl[idx] = __float2bfloat16(v - __bfloat162float(hh));
        }
    } else {
        int j = i - NQKV * DIMM;
        float v = Wp[j];
        __nv_bfloat16 hh = __float2bfloat16(v);
        g_wph[j] = hh;
        g_wpl[j] = __float2bfloat16(v - __bfloat162float(hh));
    }
}

// ---------------- k1: PE add; write fp32 + bf16 splits ----------------------------
__global__ void k1_pe(const float* __restrict__ x, const float* __restrict__ pos,
                      const float* __restrict__ Wpe, const float* __restrict__ bpe) {
    int ball = blockIdx.x;
    int tid  = threadIdx.x;
    __shared__ float rel[MB][3];
    if (tid < 3) {
        float s = 0.f;
        for (int m = 0; m < MB; m++) s += pos[(ball * MB + m) * 3 + tid];
        float mean = s * (1.f / MB);
        for (int m = 0; m < MB; m++)
            rel[m][tid] = pos[(ball * MB + m) * 3 + tid] - mean;
    }
    __syncthreads();
    int d = tid;
    float w0 = Wpe[d * 3 + 0], w1 = Wpe[d * 3 + 1], w2 = Wpe[d * 3 + 2];
    float b  = bpe[d];
    #pragma unroll
    for (int m = 0; m < MB; m++) {
        int t = ball * MB + m;
        float v = x[t * DIMM + d]
                + rel[m][0] * w0 + rel[m][1] * w1 + rel[m][2] * w2 + b;
        g_xp[t * DIMM + d] = v;
        __nv_bfloat16 h = __float2bfloat16(v);
        g_xph[t * DIMM + d] = h;
        g_xpl[t * DIMM + d] = __float2bfloat16(v - __bfloat162float(h));
    }
}

// ---------------- fp32 f32x2 GEMM-NT for Q,K (N=512), reg-prefetch pipelined ------
__global__ void __launch_bounds__(256, 2)
k2_qk(const float* __restrict__ bias) {
    __shared__ float As[2][16 * 132];
    __shared__ float Bs[2][16 * 132];
    int tid = threadIdx.x;
    int tx = tid & 15, ty = tid >> 4;
    int row0 = blockIdx.x * 128, col0 = blockIdx.y * 128;
    int r  = tid & 127;
    int k8 = (tid >> 7) * 8;

    const float* Ap = g_xp  + (row0 + r) * DIMM + k8;
    const float* Bp = g_wqk + (col0 + r) * DIMM + k8;

    float4 pa0 = *(const float4*)(Ap);
    float4 pa1 = *(const float4*)(Ap + 4);
    float4 pb0 = *(const float4*)(Bp);
    float4 pb1 = *(const float4*)(Bp + 4);

    ull accp[8][4] = {};
    #pragma unroll 2
    for (int c = 0; c < 16; c++) {
        float* A = As[c & 1];
        float* B = Bs[c & 1];
        A[(k8 + 0) * 132 + r] = pa0.x; A[(k8 + 1) * 132 + r] = pa0.y;
        A[(k8 + 2) * 132 + r] = pa0.z; A[(k8 + 3) * 132 + r] = pa0.w;
        A[(k8 + 4) * 132 + r] = pa1.x; A[(k8 + 5) * 132 + r] = pa1.y;
        A[(k8 + 6) * 132 + r] = pa1.z; A[(k8 + 7) * 132 + r] = pa1.w;
        B[(k8 + 0) * 132 + r] = pb0.x; B[(k8 + 1) * 132 + r] = pb0.y;
        B[(k8 + 2) * 132 + r] = pb0.z; B[(k8 + 3) * 132 + r] = pb0.w;
        B[(k8 + 4) * 132 + r] = pb1.x; B[(k8 + 5) * 132 + r] = pb1.y;
        B[(k8 + 6) * 132 + r] = pb1.z; B[(k8 + 7) * 132 + r] = pb1.w;
        __syncthreads();
        if (c < 15) {
            int k0n = (c + 1) * 16;
            pa0 = *(const float4*)(Ap + k0n);
            pa1 = *(const float4*)(Ap + k0n + 4);
            pb0 = *(const float4*)(Bp + k0n);
            pb1 = *(const float4*)(Bp + k0n + 4);
        }
        #pragma unroll
        for (int kk = 0; kk < 16; kk++) {
            float4 a0 = *(const float4*)(A + kk * 132 + ty * 4);
            float4 a1 = *(const float4*)(A + kk * 132 + 64 + ty * 4);
            float4 b0 = *(const float4*)(B + kk * 132 + tx * 4);
            float4 b1 = *(const float4*)(B + kk * 132 + 64 + tx * 4);
            ull bp[4] = {pack2(b0.x, b0.y), pack2(b0.z, b0.w),
                         pack2(b1.x, b1.y), pack2(b1.z, b1.w)};
            float av[8] = {a0.x, a0.y, a0.z, a0.w, a1.x, a1.y, a1.z, a1.w};
            #pragma unroll
            for (int i = 0; i < 8; i++) {
                ull ap = pack2(av[i], av[i]);
                #pragma unroll
                for (int j = 0; j < 4; j++) accp[i][j] = fma2(ap, bp[j], accp[i][j]);
            }
        }
    }
    float acc[8][8];
    #pragma unroll
    for (int i = 0; i < 8; i++)
        #pragma unroll
        for (int j = 0; j < 4; j++)
            unpack2(accp[i][j], acc[i][2 * j], acc[i][2 * j + 1]);
    #pragma unroll
    for (int i = 0; i < 8; i++) {
        int rr = row0 + ((i < 4) ? ty * 4 + i : 64 + ty * 4 + i - 4);
        #pragma unroll
        for (int j = 0; j < 8; j++) {
            int cp = col0 + ((j < 4) ? tx * 4 + j : 64 + tx * 4 + j - 4);
            int h = cp >> 6, r6 = cp & 63;
            int e = r6 >> 1, s = r6 & 1;
            float v = acc[i][j] + bias[h * 96 + e * 3 + s];
            float* dst = (s == 0) ? g_q : g_k;
            dst[(h * NM + rr) * EE + e] = v;
        }
    }
}

// ---------------- split-bf16 HMMA GEMM-NT, cp.async pipelined ----------------------
template<int MODE>
__device__ __forceinline__ void issue_chunk(uint32_t stage, int row0, int col0,
                                            int k0, int tid) {
    const __nv_bfloat16* srcs[4] = {
        (MODE == 0) ? g_xph : g_aoh, (MODE == 0) ? g_xpl : g_aol,
        (MODE == 0) ? g_wvh : g_wph, (MODE == 0) ? g_wvl : g_wpl};
    #pragma unroll
    for (int b = 0; b < 4; b++) {
        int rbase = (b < 2) ? row0 : col0;
        #pragma unroll
        for (int l = 0; l < 4; l++) {
            int u = tid + l * 256;
            int r = u >> 3, cc = u & 7;
            const void* g = srcs[b] + (rbase + r) * DIMM + k0 + cc * 8;
            uint32_t off = (uint32_t)(r * 128 + cc * 16);
            off ^= (off >> 3) & 0x70;
            cpasync16(stage + b * 16384 + off, g);
        }
    }
    asm volatile("cp.async.commit_group;" ::: "memory");
}

template<int MODE>
__global__ void __launch_bounds__(256, 1)
gemm_mma(const float* __restrict__ bias, float* __restrict__ out) {
    extern __shared__ char dsm_raw[];
    int tid = threadIdx.x;
    int wid = tid >> 5, lane = tid & 31;
    int row0 = blockIdx.x * 128, col0 = blockIdx.y * 128;
    int warp_m = (wid & 1) * 64;
    int warp_n = (wid >> 1) * 32;

    uint32_t raw = smem_u32(dsm_raw);
    uint32_t sbase = (raw + 1023u) & ~1023u;

    float acc[4][4][4] = {};
    int lr = lane & 7;
    int g  = lane >> 3;

    issue_chunk<MODE>(sbase, row0, col0, 0, tid);

    for (int chunk = 0; chunk < 4; chunk++) {
        if (chunk < 3)
            issue_chunk<MODE>(sbase + ((chunk + 1) & 1) * 65536,
                              row0, col0, (chunk + 1) * 64, tid);
        if (chunk < 3)
            asm volatile("cp.async.wait_group 1;" ::: "memory");
        else
            asm volatile("cp.async.wait_group 0;" ::: "memory");
        __syncthreads();

        uint32_t st = sbase + (chunk & 1) * 65536;
        uint32_t aBuf[2] = {st, st + 16384};
        uint32_t bBuf[2] = {st + 32768, st + 49152};

        #pragma unroll
        for (int pass = 0; pass < 3; pass++) {
            uint32_t abase = aBuf[(pass == 2) ? 1 : 0];
            uint32_t bbase = bBuf[(pass == 1) ? 1 : 0];
            #pragma unroll
            for (int ks = 0; ks < 4; ks++) {
                uint32_t af[4][4];
                #pragma unroll
                for (int mi = 0; mi < 4; mi++) {
                    int row = warp_m + mi * 16 + ((g & 1) << 3) + lr;
                    int cb  = ks * 32 + ((g >> 1) << 4);
                    ldsm4(af[mi][0], af[mi][1], af[mi][2], af[mi][3],
                          swz_addr(abase, row, cb));
                }
                uint32_t bf[4][2];
                #pragma unroll
                for (int p = 0; p < 2; p++) {
                    int n  = warp_n + p * 16 + ((g >> 1) << 3) + lr;
                    int cb = ks * 32 + ((g & 1) << 4);
                    uint32_t r0, r1, r2, r3;
                    ldsm4(r0, r1, r2, r3, swz_addr(bbase, n, cb));
                    bf[p * 2 + 0][0] = r0; bf[p * 2 + 0][1] = r1;
                    bf[p * 2 + 1][0] = r2; bf[p * 2 + 1][1] = r3;
                }
                #pragma unroll
                for (int mi = 0; mi < 4; mi++)
                    #pragma unroll
                    for (int nj = 0; nj < 4; nj++)
                        mma16816(acc[mi][nj], af[mi], bf[nj][0], bf[nj][1]);
            }
        }
        __syncthreads();
    }

    int erow = lane >> 2;
    int ecol = (lane & 3) * 2;
    #pragma unroll
    for (int mi = 0; mi < 4; mi++) {
        #pragma unroll
        for (int nj = 0; nj < 4; nj++) {
            #pragma unroll
            for (int half = 0; half < 2; half++) {
                int r = row0 + warp_m + mi * 16 + erow + half * 8;
                #pragma unroll
                for (int rg = 0; rg < 2; rg++) {
                    int cp = col0 + warp_n + nj * 8 + ecol + rg;
                    if (MODE == 0) {
                        int h = cp >> 5, e = cp & 31;
                        float v = acc[mi][nj][half * 2 + rg] + bias[h * 96 + e * 3 + 2];
                        g_vh[(h * NM + r) * EE + e] = __float2half(v);
                    } else {
                        float v = acc[mi][nj][half * 2 + rg] + bias[cp];
                        out[r * DIMM + cp] = v;
                    }
                }
            }
        }
    }
}

// ---------------- k3: per-ball key means --------------------------------------------
__global__ void k3_kmean() {
    int t = blockIdx.x * blockDim.x + threadIdx.x;
    int e = t & 31;
    int ball = (t >> 5) & (NB - 1);
    int h = t >> 14;
    const float* base = g_k + (h * NM + ball * MB) * EE + e;
    float s = 0.f;
    #pragma unroll
    for (int m = 0; m < MB; m++) s += base[m * EE];
    g_kmean[t] = s * (1.f / MB);
}

// ---------------- k4: sim GEMM + in-register top-2, double-buffered B ---------------
__global__ void __launch_bounds__(256)
k4_top2() {
    extern __shared__ float k4sm[];
    float* As = k4sm;               // 32*132
    float* Bbuf = k4sm + 32 * 132;  // 2 x 32*132
    int h = blockIdx.y;
    int tok0 = blockIdx.x * 128;
    int tid = threadIdx.x;
    int tx = tid & 15, ty = tid >> 4;

    // stage q block (k-major) and B tile 0
    #pragma unroll
    for (int l = 0; l < 4; l++) {
        int i = tid + l * 256;
        int t = i >> 3;
        int e4 = i & 7;
        float4 v = *(const float4*)(g_q + (h * NM + tok0 + t) * EE + e4 * 4);
        As[(e4 * 4 + 0) * 132 + t] = v.x;
        As[(e4 * 4 + 1) * 132 + t] = v.y;
        As[(e4 * 4 + 2) * 132 + t] = v.z;
        As[(e4 * 4 + 3) * 132 + t] = v.w;
        float4 b = *(const float4*)(g_kmean + (h * NB + t) * EE + e4 * 4);
        Bbuf[(e4 * 4 + 0) * 132 + t] = b.x;
        Bbuf[(e4 * 4 + 1) * 132 + t] = b.y;
        Bbuf[(e4 * 4 + 2) * 132 + t] = b.z;
        Bbuf[(e4 * 4 + 3) * 132 + t] = b.w;
    }
    __syncthreads();

    float v1[8], v2[8];
    int   i1[8], i2[8];
    #pragma unroll
    for (int i = 0; i < 8; i++) { v1[i] = -1e30f; v2[i] = -1e30f; i1[i] = 0; i2[i] = 0; }

    float4 pf[4];
    for (int tile = 0; tile < 4; tile++) {
        int ball0 = tile * 128;
        float* Bs = Bbuf + (tile & 1) * 32 * 132;

        if (tile < 3) {
            const float4* src = (const float4*)(g_kmean + (h * NB + ball0 + 128) * EE);
            #pragma unroll
            for (int l = 0; l < 4; l++) pf[l] = src[tid + 256 * l];
        }

        ull accp[8][4] = {};
        #pragma unroll
        for (int kk = 0; kk < 32; kk++) {
            float4 a0 = *(const float4*)(As + kk * 132 + ty * 4);
            float4 a1 = *(const float4*)(As + kk * 132 + 64 + ty * 4);
            float4 b0 = *(const float4*)(Bs + kk * 132 + tx * 4);
            float4 b1 = *(const float4*)(Bs + kk * 132 + 64 + tx * 4);
            ull bp[4] = {pack2(b0.x, b0.y), pack2(b0.z, b0.w),
                         pack2(b1.x, b1.y), pack2(b1.z, b1.w)};
            float av[8] = {a0.x, a0.y, a0.z, a0.w, a1.x, a1.y, a1.z, a1.w};
            #pragma unroll
            for (int i = 0; i < 8; i++) {
                ull ap = pack2(av[i], av[i]);
                #pragma unroll
                for (int j = 0; j < 4; j++) accp[i][j] = fma2(ap, bp[j], accp[i][j]);
            }
        }
        __syncthreads();

        if (tile < 3) {
            float* Bn = Bbuf + ((tile + 1) & 1) * 32 * 132;
            #pragma unroll
            for (int l = 0; l < 4; l++) {
                int i = tid + l * 256;
                int b = i >> 3;
                int e4 = i & 7;
                Bn[(e4 * 4 + 0) * 132 + b] = pf[l].x;
                Bn[(e4 * 4 + 1) * 132 + b] = pf[l].y;
                Bn[(e4 * 4 + 2) * 132 + b] = pf[l].z;
                Bn[(e4 * 4 + 3) * 132 + b] = pf[l].w;
            }
            __syncthreads();
        }

        #pragma unroll
        for (int i = 0; i < 8; i++) {
            #pragma unroll
            for (int j = 0; j < 4; j++) {
                float slo, shi;
                unpack2(accp[i][j], slo, shi);
                int cbase = (j < 2) ? tx * 4 + j * 2 : 64 + tx * 4 + (j - 2) * 2;
                int blo = ball0 + cbase;
                int bhi = blo + 1;
                if (slo > v1[i]) { v2[i] = v1[i]; i2[i] = i1[i]; v1[i] = slo; i1[i] = blo; }
                else if (slo > v2[i]) { v2[i] = slo; i2[i] = blo; }
                if (shi > v1[i]) { v2[i] = v1[i]; i2[i] = i1[i]; v1[i] = shi; i1[i] = bhi; }
                else if (shi > v2[i]) { v2[i] = shi; i2[i] = bhi; }
            }
        }
    }

    #pragma unroll
    for (int i = 0; i < 8; i++) {
        float a1v = v1[i], a2v = v2[i];
        int   a1i = i1[i], a2i = i2[i];
        #pragma unroll
        for (int m = 1; m < 16; m <<= 1) {
            float o1v = __shfl_xor_sync(0xffffffffu, a1v, m);
            float o2v = __shfl_xor_sync(0xffffffffu, a2v, m);
            int   o1i = __shfl_xor_sync(0xffffffffu, a1i, m);
            int   o2i = __shfl_xor_sync(0xffffffffu, a2i, m);
            if (o1v > a1v) {
                if (a1v > o2v) { a2v = a1v; a2i = a1i; }
                else           { a2v = o2v; a2i = o2i; }
                a1v = o1v; a1i = o1i;
            } else {
                if (o1v > a2v) { a2v = o1v; a2i = o1i; }
            }
        }
        if (tx == 0) {
            int tok = tok0 + ((i < 4) ? ty * 4 + i : 64 + ty * 4 + i - 4);
            g_idx[(h * NM + tok) * 2 + 0] = a1i;
            g_idx[(h * NM + tok) * 2 + 1] = a2i;
        }
    }
}

// ---------------- k5: gathered 32-key attention (fp16 V) + bf16 split out -----------
__global__ void k5_attn() {
    int warp = (blockIdx.x * blockDim.x + threadIdx.x) >> 5;
    int lane = threadIdx.x & 31;
    int h = warp >> 13;
    int tok = warp & (NM - 1);
    int b0 = g_idx[warp * 2 + 0];
    int b1 = g_idx[warp * 2 + 1];

    int ball = (lane < 16) ? b0 : b1;
    int ktok = ball * MB + (lane & 15);
    const float4* krow = (const float4*)(g_k + (h * NM + ktok) * EE);
    const float4* qrow = (const float4*)(g_q + (h * NM + tok) * EE);
    float logit = 0.f;
    #pragma unroll
    for (int e = 0; e < 8; e++) {
        float4 qv = qrow[e], kv = krow[e];
        logit += qv.x * kv.x + qv.y * kv.y + qv.z * kv.z + qv.w * kv.w;
    }
    logit *= 0.17677669529663688f;

    float m = logit;
    #pragma unroll
    for (int off = 16; off > 0; off >>= 1)
        m = fmaxf(m, __shfl_xor_sync(0xffffffffu, m, off));
    float p = __expf(logit - m);
    float s = p;
    #pragma unroll
    for (int off = 16; off > 0; off >>= 1)
        s += __shfl_xor_sync(0xffffffffu, s, off);
    float attn = p / s;

    float out = 0.f;
    #pragma unroll
    for (int kk = 0; kk < NKEY; kk++) {
        float a = __shfl_sync(0xffffffffu, attn, kk);
        int kt = ((kk < 16) ? b0 : b1) * MB + (kk & 15);
        out += a * __half2float(g_vh[(h * NM + kt) * EE + lane]);
    }
    int oi = tok * DIMM + h * EE + lane;
    __nv_bfloat16 hi = __float2bfloat16(out);
    g_aoh[oi] = hi;
    g_aol[oi] = __float2bfloat16(out - __bfloat162float(hi));
}

// ---------------- launch --------------------------------------------------------------
extern "C" void kernel_launch(void* const* d_in, const int* in_sizes, int n_in,
                              void* d_out, int out_size) {
    const float* x     = (const float*)d_in[0];
    const float* pos   = (const float*)d_in[1];
    const float* Wqkv  = (const float*)d_in[2];
    const float* bqkv  = (const float*)d_in[3];
    const float* Wpe   = (const float*)d_in[4];
    const float* bpe   = (const float*)d_in[5];
    const float* Wproj = (const float*)d_in[6];
    const float* bproj = (const float*)d_in[7];
    float* out = (float*)d_out;

    const int DSMEM = 2 * 65536 + 1024;
    const int K4SM  = 3 * 32 * 132 * 4;
    cudaFuncSetAttribute(gemm_mma<0>, cudaFuncAttributeMaxDynamicSharedMemorySize, DSMEM);
    cudaFuncSetAttribute(gemm_mma<1>, cudaFuncAttributeMaxDynamicSharedMemorySize, DSMEM);
    cudaFuncSetAttribute(k4_top2, cudaFuncAttributeMaxDynamicSharedMemorySize, K4SM);

    kconv_w<<<1024, 256>>>(Wqkv, Wproj);
    k1_pe<<<NB, 256>>>(x, pos, Wpe, bpe);
    k2_qk<<<dim3(NM / 128, 512 / 128), 256>>>(bqkv);
    gemm_mma<0><<<dim3(NM / 128, 256 / 128), 256, DSMEM>>>(bqkv, nullptr);
    k3_kmean<<<(NH * NB * EE) / 256, 256>>>();
    k4_top2<<<dim3(NM / 128, NH), 256, K4SM>>>();
    k5_attn<<<(NH * NM * 32) / 256, 256>>>();
    gemm_mma<1><<<dim3(NM / 128, DIMM / 128), 256, DSMEM>>>(bproj, out);
}

// round 9
// speedup vs baseline: 1.0835x; 1.0835x over previous
#include <cuda_runtime.h>
#include <cuda_bf16.h>
#include <cuda_fp16.h>
#include <cstdint>

#define NM   8192
#define DIMM 256
#define NH   8
#define EE   32
#define MB   16
#define NB   512
#define NKEY 32
#define NQKV 768

// ---------------- scratch ----------------------------------------------------
__device__ float g_xp[NM * DIMM];                         // fp32 PE'd x
__device__ __align__(16) __nv_bfloat16 g_xph[NM * DIMM];  // bf16 splits of xp
__device__ __align__(16) __nv_bfloat16 g_xpl[NM * DIMM];
__device__ float g_wqk[512 * DIMM];                       // permuted fp32 Q,K weights
__device__ __align__(16) __nv_bfloat16 g_wvh[256 * DIMM]; // permuted V weight splits
__device__ __align__(16) __nv_bfloat16 g_wvl[256 * DIMM];
__device__ __align__(16) __nv_bfloat16 g_wph[DIMM * DIMM];
__device__ __align__(16) __nv_bfloat16 g_wpl[DIMM * DIMM];
__device__ __align__(16) __nv_bfloat16 g_aoh[NM * DIMM];
__device__ __align__(16) __nv_bfloat16 g_aol[NM * DIMM];
__device__ float g_q[NH * NM * EE];
__device__ float g_k[NH * NM * EE];
__device__ __align__(16) __half g_vh[NH * NM * EE];       // V in fp16
__device__ float g_kmean[NH * NB * EE];
__device__ int   g_idx[NH * NM * 2];

// ---------------- packed f32x2 helpers ----------------------------------------
typedef unsigned long long ull;
__device__ __forceinline__ ull pack2(float x, float y) {
    ull r; asm("mov.b64 %0, {%1, %2};" : "=l"(r) : "f"(x), "f"(y)); return r;
}
__device__ __forceinline__ ull fma2(ull a, ull b, ull c) {
    ull d; asm("fma.rn.f32x2 %0, %1, %2, %3;" : "=l"(d) : "l"(a), "l"(b), "l"(c));
    return d;
}
__device__ __forceinline__ void unpack2(ull v, float& lo, float& hi) {
    asm("mov.b64 {%0, %1}, %2;" : "=f"(lo), "=f"(hi) : "l"(v));
}

// ---------------- mma.sync helpers ---------------------------------------------
__device__ __forceinline__ uint32_t smem_u32(const void* p) {
    uint32_t a;
    asm("{ .reg .u64 t; cvta.to.shared.u64 t, %1; cvt.u32.u64 %0, t; }" : "=r"(a) : "l"(p));
    return a;
}
__device__ __forceinline__ uint32_t swz_addr(uint32_t base, int r, int cb) {
    uint32_t off = (uint32_t)(r * 128 + cb);
    off ^= (off >> 3) & 0x70;
    return base + off;
}
__device__ __forceinline__ void ldsm4(uint32_t& r0, uint32_t& r1, uint32_t& r2,
                                      uint32_t& r3, uint32_t addr) {
    asm volatile("ldmatrix.sync.aligned.m8n8.x4.shared.b16 {%0,%1,%2,%3}, [%4];"
                 : "=r"(r0), "=r"(r1), "=r"(r2), "=r"(r3) : "r"(addr));
}
__device__ __forceinline__ void mma16816(float* d, const uint32_t* a,
                                         uint32_t b0, uint32_t b1) {
    asm volatile(
        "mma.sync.aligned.m16n8k16.row.col.f32.bf16.bf16.f32 "
        "{%0,%1,%2,%3}, {%4,%5,%6,%7}, {%8,%9}, {%0,%1,%2,%3};"
        : "+f"(d[0]), "+f"(d[1]), "+f"(d[2]), "+f"(d[3])
        : "r"(a[0]), "r"(a[1]), "r"(a[2]), "r"(a[3]), "r"(b0), "r"(b1));
}
__device__ __forceinline__ void cpasync16(uint32_t dst, const void* src) {
    asm volatile("cp.async.cg.shared.global [%0], [%1], 16;" :: "r"(dst), "l"(src));
}

// ---------------- k0: weight permutation + splits --------------------------------
__global__ void kconv_w(const float* __restrict__ Wq, const float* __restrict__ Wp) {
    int i = blockIdx.x * 256 + threadIdx.x;    // 1024 blocks
    if (i < NQKV * DIMM) {
        int c = i >> 8, d = i & 255;
        int h = c / 96, t = c % 96, e = t / 3, s = t - e * 3;
        float v = Wq[i];
        if (s < 2) {
            g_wqk[(h * 64 + e * 2 + s) * DIMM + d] = v;
        } else {
            __nv_bfloat16 hh = __float2bfloat16(v);
            int idx = (h * 32 + e) * DIMM + d;
            g_wvh[idx] = hh;
            g_wvl[idx] = __float2bfloat16(v - __bfloat162float(hh));
        }
    } else {
        int j = i - NQKV * DIMM;
        float v = Wp[j];
        __nv_bfloat16 hh = __float2bfloat16(v);
        g_wph[j] = hh;
        g_wpl[j] = __float2bfloat16(v - __bfloat162float(hh));
    }
}

// ---------------- k1: PE add; write fp32 + bf16 splits ----------------------------
__global__ void k1_pe(const float* __restrict__ x, const float* __restrict__ pos,
                      const float* __restrict__ Wpe, const float* __restrict__ bpe) {
    int ball = blockIdx.x;
    int tid  = threadIdx.x;
    __shared__ float rel[MB][3];
    if (tid < 3) {
        float s = 0.f;
        for (int m = 0; m < MB; m++) s += pos[(ball * MB + m) * 3 + tid];
        float mean = s * (1.f / MB);
        for (int m = 0; m < MB; m++)
            rel[m][tid] = pos[(ball * MB + m) * 3 + tid] - mean;
    }
    __syncthreads();
    int d = tid;
    float w0 = Wpe[d * 3 + 0], w1 = Wpe[d * 3 + 1], w2 = Wpe[d * 3 + 2];
    float b  = bpe[d];
    #pragma unroll
    for (int m = 0; m < MB; m++) {
        int t = ball * MB + m;
        float v = x[t * DIMM + d]
                + rel[m][0] * w0 + rel[m][1] * w1 + rel[m][2] * w2 + b;
        g_xp[t * DIMM + d] = v;
        __nv_bfloat16 h = __float2bfloat16(v);
        g_xph[t * DIMM + d] = h;
        g_xpl[t * DIMM + d] = __float2bfloat16(v - __bfloat162float(h));
    }
}

// ---------------- fp32 f32x2 GEMM-NT for Q,K (N=512), reg-prefetch pipelined ------
__global__ void __launch_bounds__(256, 2)
k2_qk(const float* __restrict__ bias) {
    __shared__ float As[2][16 * 132];
    __shared__ float Bs[2][16 * 132];
    int tid = threadIdx.x;
    int tx = tid & 15, ty = tid >> 4;
    int row0 = blockIdx.x * 128, col0 = blockIdx.y * 128;
    int r  = tid & 127;
    int k8 = (tid >> 7) * 8;

    const float* Ap = g_xp  + (row0 + r) * DIMM + k8;
    const float* Bp = g_wqk + (col0 + r) * DIMM + k8;

    float4 pa0 = *(const float4*)(Ap);
    float4 pa1 = *(const float4*)(Ap + 4);
    float4 pb0 = *(const float4*)(Bp);
    float4 pb1 = *(const float4*)(Bp + 4);

    ull accp[8][4] = {};
    #pragma unroll 2
    for (int c = 0; c < 16; c++) {
        float* A = As[c & 1];
        float* B = Bs[c & 1];
        A[(k8 + 0) * 132 + r] = pa0.x; A[(k8 + 1) * 132 + r] = pa0.y;
        A[(k8 + 2) * 132 + r] = pa0.z; A[(k8 + 3) * 132 + r] = pa0.w;
        A[(k8 + 4) * 132 + r] = pa1.x; A[(k8 + 5) * 132 + r] = pa1.y;
        A[(k8 + 6) * 132 + r] = pa1.z; A[(k8 + 7) * 132 + r] = pa1.w;
        B[(k8 + 0) * 132 + r] = pb0.x; B[(k8 + 1) * 132 + r] = pb0.y;
        B[(k8 + 2) * 132 + r] = pb0.z; B[(k8 + 3) * 132 + r] = pb0.w;
        B[(k8 + 4) * 132 + r] = pb1.x; B[(k8 + 5) * 132 + r] = pb1.y;
        B[(k8 + 6) * 132 + r] = pb1.z; B[(k8 + 7) * 132 + r] = pb1.w;
        __syncthreads();
        if (c < 15) {
            int k0n = (c + 1) * 16;
            pa0 = *(const float4*)(Ap + k0n);
            pa1 = *(const float4*)(Ap + k0n + 4);
            pb0 = *(const float4*)(Bp + k0n);
            pb1 = *(const float4*)(Bp + k0n + 4);
        }
        #pragma unroll
        for (int kk = 0; kk < 16; kk++) {
            float4 a0 = *(const float4*)(A + kk * 132 + ty * 4);
            float4 a1 = *(const float4*)(A + kk * 132 + 64 + ty * 4);
            float4 b0 = *(const float4*)(B + kk * 132 + tx * 4);
            float4 b1 = *(const float4*)(B + kk * 132 + 64 + tx * 4);
            ull bp[4] = {pack2(b0.x, b0.y), pack2(b0.z, b0.w),
                         pack2(b1.x, b1.y), pack2(b1.z, b1.w)};
            float av[8] = {a0.x, a0.y, a0.z, a0.w, a1.x, a1.y, a1.z, a1.w};
            #pragma unroll
            for (int i = 0; i < 8; i++) {
                ull ap = pack2(av[i], av[i]);
                #pragma unroll
                for (int j = 0; j < 4; j++) accp[i][j] = fma2(ap, bp[j], accp[i][j]);
            }
        }
    }
    float acc[8][8];
    #pragma unroll
    for (int i = 0; i < 8; i++)
        #pragma unroll
        for (int j = 0; j < 4; j++)
            unpack2(accp[i][j], acc[i][2 * j], acc[i][2 * j + 1]);
    #pragma unroll
    for (int i = 0; i < 8; i++) {
        int rr = row0 + ((i < 4) ? ty * 4 + i : 64 + ty * 4 + i - 4);
        #pragma unroll
        for (int j = 0; j < 8; j++) {
            int cp = col0 + ((j < 4) ? tx * 4 + j : 64 + tx * 4 + j - 4);
            int h = cp >> 6, r6 = cp & 63;
            int e = r6 >> 1, s = r6 & 1;
            float v = acc[i][j] + bias[h * 96 + e * 3 + s];
            float* dst = (s == 0) ? g_q : g_k;
            dst[(h * NM + rr) * EE + e] = v;
        }
    }
}

// ---------------- split-bf16 HMMA GEMM-NT, cp.async pipelined ----------------------
template<int MODE>
__device__ __forceinline__ void issue_chunk(uint32_t stage, int row0, int col0,
                                            int k0, int tid) {
    const __nv_bfloat16* srcs[4] = {
        (MODE == 0) ? g_xph : g_aoh, (MODE == 0) ? g_xpl : g_aol,
        (MODE == 0) ? g_wvh : g_wph, (MODE == 0) ? g_wvl : g_wpl};
    #pragma unroll
    for (int b = 0; b < 4; b++) {
        int rbase = (b < 2) ? row0 : col0;
        #pragma unroll
        for (int l = 0; l < 4; l++) {
            int u = tid + l * 256;
            int r = u >> 3, cc = u & 7;
            const void* g = srcs[b] + (rbase + r) * DIMM + k0 + cc * 8;
            uint32_t off = (uint32_t)(r * 128 + cc * 16);
            off ^= (off >> 3) & 0x70;
            cpasync16(stage + b * 16384 + off, g);
        }
    }
    asm volatile("cp.async.commit_group;" ::: "memory");
}

template<int MODE>
__global__ void __launch_bounds__(256, 1)
gemm_mma(const float* __restrict__ bias, float* __restrict__ out) {
    extern __shared__ char dsm_raw[];
    int tid = threadIdx.x;
    int wid = tid >> 5, lane = tid & 31;
    int row0 = blockIdx.x * 128, col0 = blockIdx.y * 128;
    int warp_m = (wid & 1) * 64;
    int warp_n = (wid >> 1) * 32;

    uint32_t raw = smem_u32(dsm_raw);
    uint32_t sbase = (raw + 1023u) & ~1023u;

    float acc[4][4][4] = {};
    int lr = lane & 7;
    int g  = lane >> 3;

    issue_chunk<MODE>(sbase, row0, col0, 0, tid);

    for (int chunk = 0; chunk < 4; chunk++) {
        if (chunk < 3)
            issue_chunk<MODE>(sbase + ((chunk + 1) & 1) * 65536,
                              row0, col0, (chunk + 1) * 64, tid);
        if (chunk < 3)
            asm volatile("cp.async.wait_group 1;" ::: "memory");
        else
            asm volatile("cp.async.wait_group 0;" ::: "memory");
        __syncthreads();

        uint32_t st = sbase + (chunk & 1) * 65536;
        uint32_t aBuf[2] = {st, st + 16384};
        uint32_t bBuf[2] = {st + 32768, st + 49152};

        #pragma unroll
        for (int pass = 0; pass < 3; pass++) {
            uint32_t abase = aBuf[(pass == 2) ? 1 : 0];
            uint32_t bbase = bBuf[(pass == 1) ? 1 : 0];
            #pragma unroll
            for (int ks = 0; ks < 4; ks++) {
                uint32_t af[4][4];
                #pragma unroll
                for (int mi = 0; mi < 4; mi++) {
                    int row = warp_m + mi * 16 + ((g & 1) << 3) + lr;
                    int cb  = ks * 32 + ((g >> 1) << 4);
                    ldsm4(af[mi][0], af[mi][1], af[mi][2], af[mi][3],
                          swz_addr(abase, row, cb));
                }
                uint32_t bf[4][2];
                #pragma unroll
                for (int p = 0; p < 2; p++) {
                    int n  = warp_n + p * 16 + ((g >> 1) << 3) + lr;
                    int cb = ks * 32 + ((g & 1) << 4);
                    uint32_t r0, r1, r2, r3;
                    ldsm4(r0, r1, r2, r3, swz_addr(bbase, n, cb));
                    bf[p * 2 + 0][0] = r0; bf[p * 2 + 0][1] = r1;
                    bf[p * 2 + 1][0] = r2; bf[p * 2 + 1][1] = r3;
                }
                #pragma unroll
                for (int mi = 0; mi < 4; mi++)
                    #pragma unroll
                    for (int nj = 0; nj < 4; nj++)
                        mma16816(acc[mi][nj], af[mi], bf[nj][0], bf[nj][1]);
            }
        }
        __syncthreads();
    }

    int erow = lane >> 2;
    int ecol = (lane & 3) * 2;
    #pragma unroll
    for (int mi = 0; mi < 4; mi++) {
        #pragma unroll
        for (int nj = 0; nj < 4; nj++) {
            #pragma unroll
            for (int half = 0; half < 2; half++) {
                int r = row0 + warp_m + mi * 16 + erow + half * 8;
                #pragma unroll
                for (int rg = 0; rg < 2; rg++) {
                    int cp = col0 + warp_n + nj * 8 + ecol + rg;
                    if (MODE == 0) {
                        int h = cp >> 5, e = cp & 31;
                        float v = acc[mi][nj][half * 2 + rg] + bias[h * 96 + e * 3 + 2];
                        g_vh[(h * NM + r) * EE + e] = __float2half(v);
                    } else {
                        float v = acc[mi][nj][half * 2 + rg] + bias[cp];
                        out[r * DIMM + cp] = v;
                    }
                }
            }
        }
    }
}

// ---------------- k3: per-ball key means --------------------------------------------
__global__ void k3_kmean() {
    int t = blockIdx.x * blockDim.x + threadIdx.x;
    int e = t & 31;
    int ball = (t >> 5) & (NB - 1);
    int h = t >> 14;
    const float* base = g_k + (h * NM + ball * MB) * EE + e;
    float s = 0.f;
    #pragma unroll
    for (int m = 0; m < MB; m++) s += base[m * EE];
    g_kmean[t] = s * (1.f / MB);
}

// ---------------- k4: sim GEMM + in-register top-2 (round-3 proven version) ---------
__global__ void __launch_bounds__(256)
k4_top2() {
    __shared__ float As[32 * 132];
    __shared__ float Bs[32 * 132];
    int h = blockIdx.y;
    int tok0 = blockIdx.x * 128;
    int tid = threadIdx.x;
    int tx = tid & 15, ty = tid >> 4;

    #pragma unroll
    for (int l = 0; l < 4; l++) {
        int i = tid + l * 256;
        int t = i >> 3;
        int e4 = i & 7;
        float4 v = *(const float4*)(g_q + (h * NM + tok0 + t) * EE + e4 * 4);
        As[(e4 * 4 + 0) * 132 + t] = v.x;
        As[(e4 * 4 + 1) * 132 + t] = v.y;
        As[(e4 * 4 + 2) * 132 + t] = v.z;
        As[(e4 * 4 + 3) * 132 + t] = v.w;
    }

    float v1[8], v2[8];
    int   i1[8], i2[8];
    #pragma unroll
    for (int i = 0; i < 8; i++) { v1[i] = -1e30f; v2[i] = -1e30f; i1[i] = 0; i2[i] = 0; }

    for (int tile = 0; tile < 4; tile++) {
        int ball0 = tile * 128;
        __syncthreads();
        #pragma unroll
        for (int l = 0; l < 4; l++) {
            int i = tid + l * 256;
            int b = i >> 3;
            int e4 = i & 7;
            float4 v = *(const float4*)(g_kmean + (h * NB + ball0 + b) * EE + e4 * 4);
            Bs[(e4 * 4 + 0) * 132 + b] = v.x;
            Bs[(e4 * 4 + 1) * 132 + b] = v.y;
            Bs[(e4 * 4 + 2) * 132 + b] = v.z;
            Bs[(e4 * 4 + 3) * 132 + b] = v.w;
        }
        __syncthreads();

        ull accp[8][4] = {};
        #pragma unroll
        for (int kk = 0; kk < 32; kk++) {
            float4 a0 = *(const float4*)(As + kk * 132 + ty * 4);
            float4 a1 = *(const float4*)(As + kk * 132 + 64 + ty * 4);
            float4 b0 = *(const float4*)(Bs + kk * 132 + tx * 4);
            float4 b1 = *(const float4*)(Bs + kk * 132 + 64 + tx * 4);
            ull bp[4] = {pack2(b0.x, b0.y), pack2(b0.z, b0.w),
                         pack2(b1.x, b1.y), pack2(b1.z, b1.w)};
            float av[8] = {a0.x, a0.y, a0.z, a0.w, a1.x, a1.y, a1.z, a1.w};
            #pragma unroll
            for (int i = 0; i < 8; i++) {
                ull ap = pack2(av[i], av[i]);
                #pragma unroll
                for (int j = 0; j < 4; j++) accp[i][j] = fma2(ap, bp[j], accp[i][j]);
            }
        }

        #pragma unroll
        for (int i = 0; i < 8; i++) {
            #pragma unroll
            for (int j = 0; j < 4; j++) {
                float slo, shi;
                unpack2(accp[i][j], slo, shi);
                int cbase = (j < 2) ? tx * 4 + j * 2 : 64 + tx * 4 + (j - 2) * 2;
                int blo = ball0 + cbase;
                int bhi = blo + 1;
                if (slo > v1[i]) { v2[i] = v1[i]; i2[i] = i1[i]; v1[i] = slo; i1[i] = blo; }
                else if (slo > v2[i]) { v2[i] = slo; i2[i] = blo; }
                if (shi > v1[i]) { v2[i] = v1[i]; i2[i] = i1[i]; v1[i] = shi; i1[i] = bhi; }
                else if (shi > v2[i]) { v2[i] = shi; i2[i] = bhi; }
            }
        }
    }

    #pragma unroll
    for (int i = 0; i < 8; i++) {
        float a1v = v1[i], a2v = v2[i];
        int   a1i = i1[i], a2i = i2[i];
        #pragma unroll
        for (int m = 1; m < 16; m <<= 1) {
            float o1v = __shfl_xor_sync(0xffffffffu, a1v, m);
            float o2v = __shfl_xor_sync(0xffffffffu, a2v, m);
            int   o1i = __shfl_xor_sync(0xffffffffu, a1i, m);
            int   o2i = __shfl_xor_sync(0xffffffffu, a2i, m);
            if (o1v > a1v) {
                if (a1v > o2v) { a2v = a1v; a2i = a1i; }
                else           { a2v = o2v; a2i = o2i; }
                a1v = o1v; a1i = o1i;
            } else {
                if (o1v > a2v) { a2v = o1v; a2i = o1i; }
            }
        }
        if (tx == 0) {
            int tok = tok0 + ((i < 4) ? ty * 4 + i : 64 + ty * 4 + i - 4);
            g_idx[(h * NM + tok) * 2 + 0] = a1i;
            g_idx[(h * NM + tok) * 2 + 1] = a2i;
        }
    }
}

// ---------------- k5: gathered 32-key attention (fp16 V) + bf16 split out -----------
__global__ void k5_attn() {
    int warp = (blockIdx.x * blockDim.x + threadIdx.x) >> 5;
    int lane = threadIdx.x & 31;
    int h = warp >> 13;
    int tok = warp & (NM - 1);
    int b0 = g_idx[warp * 2 + 0];
    int b1 = g_idx[warp * 2 + 1];

    int ball = (lane < 16) ? b0 : b1;
    int ktok = ball * MB + (lane & 15);
    const float4* krow = (const float4*)(g_k + (h * NM + ktok) * EE);
    const float4* qrow = (const float4*)(g_q + (h * NM + tok) * EE);
    float logit = 0.f;
    #pragma unroll
    for (int e = 0; e < 8; e++) {
        float4 qv = qrow[e], kv = krow[e];
        logit += qv.x * kv.x + qv.y * kv.y + qv.z * kv.z + qv.w * kv.w;
    }
    logit *= 0.17677669529663688f;

    float m = logit;
    #pragma unroll
    for (int off = 16; off > 0; off >>= 1)
        m = fmaxf(m, __shfl_xor_sync(0xffffffffu, m, off));
    float p = __expf(logit - m);
    float s = p;
    #pragma unroll
    for (int off = 16; off > 0; off >>= 1)
        s += __shfl_xor_sync(0xffffffffu, s, off);
    float attn = p / s;

    float out = 0.f;
    #pragma unroll
    for (int kk = 0; kk < NKEY; kk++) {
        float a = __shfl_sync(0xffffffffu, attn, kk);
        int kt = ((kk < 16) ? b0 : b1) * MB + (kk & 15);
        out += a * __half2float(g_vh[(h * NM + kt) * EE + lane]);
    }
    int oi = tok * DIMM + h * EE + lane;
    __nv_bfloat16 hi = __float2bfloat16(out);
    g_aoh[oi] = hi;
    g_aol[oi] = __float2bfloat16(out - __bfloat162float(hi));
}

// ---------------- launch --------------------------------------------------------------
extern "C" void kernel_launch(void* const* d_in, const int* in_sizes, int n_in,
                              void* d_out, int out_size) {
    const float* x     = (const float*)d_in[0];
    const float* pos   = (const float*)d_in[1];
    const float* Wqkv  = (const float*)d_in[2];
    const float* bqkv  = (const float*)d_in[3];
    const float* Wpe   = (const float*)d_in[4];
    const float* bpe   = (const float*)d_in[5];
    const float* Wproj = (const float*)d_in[6];
    const float* bproj = (const float*)d_in[7];
    float* out = (float*)d_out;

    const int DSMEM = 2 * 65536 + 1024;
    cudaFuncSetAttribute(gemm_mma<0>, cudaFuncAttributeMaxDynamicSharedMemorySize, DSMEM);
    cudaFuncSetAttribute(gemm_mma<1>, cudaFuncAttributeMaxDynamicSharedMemorySize, DSMEM);

    kconv_w<<<1024, 256>>>(Wqkv, Wproj);
    k1_pe<<<NB, 256>>>(x, pos, Wpe, bpe);
    k2_qk<<<dim3(NM / 128, 512 / 128), 256>>>(bqkv);
    gemm_mma<0><<<dim3(NM / 128, 256 / 128), 256, DSMEM>>>(bqkv, nullptr);
    k3_kmean<<<(NH * NB * EE) / 256, 256>>>();
    k4_top2<<<dim3(NM / 128, NH), 256>>>();
    k5_attn<<<(NH * NM * 32) / 256, 256>>>();
    gemm_mma<1><<<dim3(NM / 128, DIMM / 128), 256, DSMEM>>>(bproj, out);
}

// round 10
// speedup vs baseline: 1.0853x; 1.0016x over previous
#include <cuda_runtime.h>
#include <cuda_bf16.h>
#include <cuda_fp16.h>
#include <cstdint>

#define NM   8192
#define DIMM 256
#define NH   8
#define EE   32
#define MB   16
#define NB   512
#define NKEY 32
#define NQKV 768

// ---------------- scratch ----------------------------------------------------
__device__ float g_xp[NM * DIMM];                         // fp32 PE'd x
__device__ __align__(16) __nv_bfloat16 g_xph[NM * DIMM];  // bf16 splits of xp
__device__ __align__(16) __nv_bfloat16 g_xpl[NM * DIMM];
__device__ float g_wqk[512 * DIMM];                       // permuted fp32 Q,K weights
__device__ __align__(16) __nv_bfloat16 g_wvh[256 * DIMM]; // permuted V weight splits
__device__ __align__(16) __nv_bfloat16 g_wvl[256 * DIMM];
__device__ __align__(16) __nv_bfloat16 g_wph[DIMM * DIMM];
__device__ __align__(16) __nv_bfloat16 g_wpl[DIMM * DIMM];
__device__ __align__(16) __nv_bfloat16 g_aoh[NM * DIMM];
__device__ __align__(16) __nv_bfloat16 g_aol[NM * DIMM];
__device__ float g_q[NH * NM * EE];
__device__ float g_k[NH * NM * EE];
__device__ __align__(16) __half g_vh[NH * NM * EE];       // V in fp16
__device__ int   g_idx[NH * NM * 2];
// 3-way bf16 splits for the selection GEMM (exact to ~2^-25)
__device__ __align__(16) __nv_bfloat16 g_q1[NH * NM * EE];
__device__ __align__(16) __nv_bfloat16 g_q2[NH * NM * EE];
__device__ __align__(16) __nv_bfloat16 g_q3[NH * NM * EE];
__device__ __align__(16) __nv_bfloat16 g_km1[NH * NB * EE];
__device__ __align__(16) __nv_bfloat16 g_km2[NH * NB * EE];
__device__ __align__(16) __nv_bfloat16 g_km3[NH * NB * EE];

// ---------------- packed f32x2 helpers ----------------------------------------
typedef unsigned long long ull;
__device__ __forceinline__ ull pack2(float x, float y) {
    ull r; asm("mov.b64 %0, {%1, %2};" : "=l"(r) : "f"(x), "f"(y)); return r;
}
__device__ __forceinline__ ull fma2(ull a, ull b, ull c) {
    ull d; asm("fma.rn.f32x2 %0, %1, %2, %3;" : "=l"(d) : "l"(a), "l"(b), "l"(c));
    return d;
}
__device__ __forceinline__ void unpack2(ull v, float& lo, float& hi) {
    asm("mov.b64 {%0, %1}, %2;" : "=f"(lo), "=f"(hi) : "l"(v));
}

// ---------------- mma.sync helpers ---------------------------------------------
__device__ __forceinline__ uint32_t smem_u32(const void* p) {
    uint32_t a;
    asm("{ .reg .u64 t; cvta.to.shared.u64 t, %1; cvt.u32.u64 %0, t; }" : "=r"(a) : "l"(p));
    return a;
}
__device__ __forceinline__ uint32_t swz_addr(uint32_t base, int r, int cb) {
    uint32_t off = (uint32_t)(r * 128 + cb);
    off ^= (off >> 3) & 0x70;
    return base + off;
}
__device__ __forceinline__ void ldsm4(uint32_t& r0, uint32_t& r1, uint32_t& r2,
                                      uint32_t& r3, uint32_t addr) {
    asm volatile("ldmatrix.sync.aligned.m8n8.x4.shared.b16 {%0,%1,%2,%3}, [%4];"
                 : "=r"(r0), "=r"(r1), "=r"(r2), "=r"(r3) : "r"(addr));
}
__device__ __forceinline__ void mma16816(float* d, const uint32_t* a,
                                         uint32_t b0, uint32_t b1) {
    asm volatile(
        "mma.sync.aligned.m16n8k16.row.col.f32.bf16.bf16.f32 "
        "{%0,%1,%2,%3}, {%4,%5,%6,%7}, {%8,%9}, {%0,%1,%2,%3};"
        : "+f"(d[0]), "+f"(d[1]), "+f"(d[2]), "+f"(d[3])
        : "r"(a[0]), "r"(a[1]), "r"(a[2]), "r"(a[3]), "r"(b0), "r"(b1));
}
__device__ __forceinline__ void cpasync16(uint32_t dst, const void* src) {
    asm volatile("cp.async.cg.shared.global [%0], [%1], 16;" :: "r"(dst), "l"(src));
}

// ---------------- k0: weight permutation + splits --------------------------------
__global__ void kconv_w(const float* __restrict__ Wq, const float* __restrict__ Wp) {
    int i = blockIdx.x * 256 + threadIdx.x;    // 1024 blocks
    if (i < NQKV * DIMM) {
        int c = i >> 8, d = i & 255;
        int h = c / 96, t = c % 96, e = t / 3, s = t - e * 3;
        float v = Wq[i];
        if (s < 2) {
            g_wqk[(h * 64 + e * 2 + s) * DIMM + d] = v;
        } else {
            __nv_bfloat16 hh = __float2bfloat16(v);
            int idx = (h * 32 + e) * DIMM + d;
            g_wvh[idx] = hh;
            g_wvl[idx] = __float2bfloat16(v - __bfloat162float(hh));
        }
    } else {
        int j = i - NQKV * DIMM;
        float v = Wp[j];
        __nv_bfloat16 hh = __float2bfloat16(v);
        g_wph[j] = hh;
        g_wpl[j] = __float2bfloat16(v - __bfloat162float(hh));
    }
}

// ---------------- k1: PE add; write fp32 + bf16 splits ----------------------------
__global__ void k1_pe(const float* __restrict__ x, const float* __restrict__ pos,
                      const float* __restrict__ Wpe, const float* __restrict__ bpe) {
    int ball = blockIdx.x;
    int tid  = threadIdx.x;
    __shared__ float rel[MB][3];
    if (tid < 3) {
        float s = 0.f;
        for (int m = 0; m < MB; m++) s += pos[(ball * MB + m) * 3 + tid];
        float mean = s * (1.f / MB);
        for (int m = 0; m < MB; m++)
            rel[m][tid] = pos[(ball * MB + m) * 3 + tid] - mean;
    }
    __syncthreads();
    int d = tid;
    float w0 = Wpe[d * 3 + 0], w1 = Wpe[d * 3 + 1], w2 = Wpe[d * 3 + 2];
    float b  = bpe[d];
    #pragma unroll
    for (int m = 0; m < MB; m++) {
        int t = ball * MB + m;
        float v = x[t * DIMM + d]
                + rel[m][0] * w0 + rel[m][1] * w1 + rel[m][2] * w2 + b;
        g_xp[t * DIMM + d] = v;
        __nv_bfloat16 h = __float2bfloat16(v);
        g_xph[t * DIMM + d] = h;
        g_xpl[t * DIMM + d] = __float2bfloat16(v - __bfloat162float(h));
    }
}

// ---------------- fp32 f32x2 GEMM-NT for Q,K (N=512), reg-prefetch pipelined ------
__global__ void __launch_bounds__(256, 2)
k2_qk(const float* __restrict__ bias) {
    __shared__ float As[2][16 * 132];
    __shared__ float Bs[2][16 * 132];
    int tid = threadIdx.x;
    int tx = tid & 15, ty = tid >> 4;
    int row0 = blockIdx.x * 128, col0 = blockIdx.y * 128;
    int r  = tid & 127;
    int k8 = (tid >> 7) * 8;

    const float* Ap = g_xp  + (row0 + r) * DIMM + k8;
    const float* Bp = g_wqk + (col0 + r) * DIMM + k8;

    float4 pa0 = *(const float4*)(Ap);
    float4 pa1 = *(const float4*)(Ap + 4);
    float4 pb0 = *(const float4*)(Bp);
    float4 pb1 = *(const float4*)(Bp + 4);

    ull accp[8][4] = {};
    #pragma unroll 2
    for (int c = 0; c < 16; c++) {
        float* A = As[c & 1];
        float* B = Bs[c & 1];
        A[(k8 + 0) * 132 + r] = pa0.x; A[(k8 + 1) * 132 + r] = pa0.y;
        A[(k8 + 2) * 132 + r] = pa0.z; A[(k8 + 3) * 132 + r] = pa0.w;
        A[(k8 + 4) * 132 + r] = pa1.x; A[(k8 + 5) * 132 + r] = pa1.y;
        A[(k8 + 6) * 132 + r] = pa1.z; A[(k8 + 7) * 132 + r] = pa1.w;
        B[(k8 + 0) * 132 + r] = pb0.x; B[(k8 + 1) * 132 + r] = pb0.y;
        B[(k8 + 2) * 132 + r] = pb0.z; B[(k8 + 3) * 132 + r] = pb0.w;
        B[(k8 + 4) * 132 + r] = pb1.x; B[(k8 + 5) * 132 + r] = pb1.y;
        B[(k8 + 6) * 132 + r] = pb1.z; B[(k8 + 7) * 132 + r] = pb1.w;
        __syncthreads();
        if (c < 15) {
            int k0n = (c + 1) * 16;
            pa0 = *(const float4*)(Ap + k0n);
            pa1 = *(const float4*)(Ap + k0n + 4);
            pb0 = *(const float4*)(Bp + k0n);
            pb1 = *(const float4*)(Bp + k0n + 4);
        }
        #pragma unroll
        for (int kk = 0; kk < 16; kk++) {
            float4 a0 = *(const float4*)(A + kk * 132 + ty * 4);
            float4 a1 = *(const float4*)(A + kk * 132 + 64 + ty * 4);
            float4 b0 = *(const float4*)(B + kk * 132 + tx * 4);
            float4 b1 = *(const float4*)(B + kk * 132 + 64 + tx * 4);
            ull bp[4] = {pack2(b0.x, b0.y), pack2(b0.z, b0.w),
                         pack2(b1.x, b1.y), pack2(b1.z, b1.w)};
            float av[8] = {a0.x, a0.y, a0.z, a0.w, a1.x, a1.y, a1.z, a1.w};
            #pragma unroll
            for (int i = 0; i < 8; i++) {
                ull ap = pack2(av[i], av[i]);
                #pragma unroll
                for (int j = 0; j < 4; j++) accp[i][j] = fma2(ap, bp[j], accp[i][j]);
            }
        }
    }
    float acc[8][8];
    #pragma unroll
    for (int i = 0; i < 8; i++)
        #pragma unroll
        for (int j = 0; j < 4; j++)
            unpack2(accp[i][j], acc[i][2 * j], acc[i][2 * j + 1]);
    #pragma unroll
    for (int i = 0; i < 8; i++) {
        int rr = row0 + ((i < 4) ? ty * 4 + i : 64 + ty * 4 + i - 4);
        #pragma unroll
        for (int j = 0; j < 8; j++) {
            int cp = col0 + ((j < 4) ? tx * 4 + j : 64 + tx * 4 + j - 4);
            int h = cp >> 6, r6 = cp & 63;
            int e = r6 >> 1, s = r6 & 1;
            float v = acc[i][j] + bias[h * 96 + e * 3 + s];
            int qi = (h * NM + rr) * EE + e;
            if (s == 0) {
                g_q[qi] = v;
                __nv_bfloat16 b1 = __float2bfloat16(v);
                float f1 = __bfloat162float(b1);
                __nv_bfloat16 b2 = __float2bfloat16(v - f1);
                float f2 = __bfloat162float(b2);
                __nv_bfloat16 b3 = __float2bfloat16(v - f1 - f2);
                g_q1[qi] = b1; g_q2[qi] = b2; g_q3[qi] = b3;
            } else {
                g_k[qi] = v;
            }
        }
    }
}

// ---------------- split-bf16 HMMA GEMM-NT, cp.async pipelined ----------------------
template<int MODE>
__device__ __forceinline__ void issue_chunk(uint32_t stage, int row0, int col0,
                                            int k0, int tid) {
    const __nv_bfloat16* srcs[4] = {
        (MODE == 0) ? g_xph : g_aoh, (MODE == 0) ? g_xpl : g_aol,
        (MODE == 0) ? g_wvh : g_wph, (MODE == 0) ? g_wvl : g_wpl};
    #pragma unroll
    for (int b = 0; b < 4; b++) {
        int rbase = (b < 2) ? row0 : col0;
        #pragma unroll
        for (int l = 0; l < 4; l++) {
            int u = tid + l * 256;
            int r = u >> 3, cc = u & 7;
            const void* g = srcs[b] + (rbase + r) * DIMM + k0 + cc * 8;
            uint32_t off = (uint32_t)(r * 128 + cc * 16);
            off ^= (off >> 3) & 0x70;
            cpasync16(stage + b * 16384 + off, g);
        }
    }
    asm volatile("cp.async.commit_group;" ::: "memory");
}

template<int MODE>
__global__ void __launch_bounds__(256, 1)
gemm_mma(const float* __restrict__ bias, float* __restrict__ out) {
    extern __shared__ char dsm_raw[];
    int tid = threadIdx.x;
    int wid = tid >> 5, lane = tid & 31;
    int row0 = blockIdx.x * 128, col0 = blockIdx.y * 128;
    int warp_m = (wid & 1) * 64;
    int warp_n = (wid >> 1) * 32;

    uint32_t raw = smem_u32(dsm_raw);
    uint32_t sbase = (raw + 1023u) & ~1023u;

    float acc[4][4][4] = {};
    int lr = lane & 7;
    int g  = lane >> 3;

    issue_chunk<MODE>(sbase, row0, col0, 0, tid);

    for (int chunk = 0; chunk < 4; chunk++) {
        if (chunk < 3)
            issue_chunk<MODE>(sbase + ((chunk + 1) & 1) * 65536,
                              row0, col0, (chunk + 1) * 64, tid);
        if (chunk < 3)
            asm volatile("cp.async.wait_group 1;" ::: "memory");
        else
            asm volatile("cp.async.wait_group 0;" ::: "memory");
        __syncthreads();

        uint32_t st = sbase + (chunk & 1) * 65536;
        uint32_t aBuf[2] = {st, st + 16384};
        uint32_t bBuf[2] = {st + 32768, st + 49152};

        #pragma unroll
        for (int pass = 0; pass < 3; pass++) {
            uint32_t abase = aBuf[(pass == 2) ? 1 : 0];
            uint32_t bbase = bBuf[(pass == 1) ? 1 : 0];
            #pragma unroll
            for (int ks = 0; ks < 4; ks++) {
                uint32_t af[4][4];
                #pragma unroll
                for (int mi = 0; mi < 4; mi++) {
                    int row = warp_m + mi * 16 + ((g & 1) << 3) + lr;
                    int cb  = ks * 32 + ((g >> 1) << 4);
                    ldsm4(af[mi][0], af[mi][1], af[mi][2], af[mi][3],
                          swz_addr(abase, row, cb));
                }
                uint32_t bf[4][2];
                #pragma unroll
                for (int p = 0; p < 2; p++) {
                    int n  = warp_n + p * 16 + ((g >> 1) << 3) + lr;
                    int cb = ks * 32 + ((g & 1) << 4);
                    uint32_t r0, r1, r2, r3;
                    ldsm4(r0, r1, r2, r3, swz_addr(bbase, n, cb));
                    bf[p * 2 + 0][0] = r0; bf[p * 2 + 0][1] = r1;
                    bf[p * 2 + 1][0] = r2; bf[p * 2 + 1][1] = r3;
                }
                #pragma unroll
                for (int mi = 0; mi < 4; mi++)
                    #pragma unroll
                    for (int nj = 0; nj < 4; nj++)
                        mma16816(acc[mi][nj], af[mi], bf[nj][0], bf[nj][1]);
            }
        }
        __syncthreads();
    }

    int erow = lane >> 2;
    int ecol = (lane & 3) * 2;
    #pragma unroll
    for (int mi = 0; mi < 4; mi++) {
        #pragma unroll
        for (int nj = 0; nj < 4; nj++) {
            #pragma unroll
            for (int half = 0; half < 2; half++) {
                int r = row0 + warp_m + mi * 16 + erow + half * 8;
                #pragma unroll
                for (int rg = 0; rg < 2; rg++) {
                    int cp = col0 + warp_n + nj * 8 + ecol + rg;
                    if (MODE == 0) {
                        int h = cp >> 5, e = cp & 31;
                        float v = acc[mi][nj][half * 2 + rg] + bias[h * 96 + e * 3 + 2];
                        g_vh[(h * NM + r) * EE + e] = __float2half(v);
                    } else {
                        float v = acc[mi][nj][half * 2 + rg] + bias[cp];
                        out[r * DIMM + cp] = v;
                    }
                }
            }
        }
    }
}

// ---------------- k3: per-ball key means -> 3-way bf16 splits ------------------------
__global__ void k3_kmean() {
    int t = blockIdx.x * blockDim.x + threadIdx.x;   // (h*NB+ball)*EE + e
    int e = t & 31;
    int ball = (t >> 5) & (NB - 1);
    int h = t >> 14;
    const float* base = g_k + (h * NM + ball * MB) * EE + e;
    float s = 0.f;
    #pragma unroll
    for (int m = 0; m < MB; m++) s += base[m * EE];
    float v = s * (1.f / MB);
    __nv_bfloat16 b1 = __float2bfloat16(v);
    float f1 = __bfloat162float(b1);
    __nv_bfloat16 b2 = __float2bfloat16(v - f1);
    float f2 = __bfloat162float(b2);
    __nv_bfloat16 b3 = __float2bfloat16(v - f1 - f2);
    g_km1[t] = b1; g_km2[t] = b2; g_km3[t] = b3;
}

// ---------------- k4: sim via HMMA 6-product 3-way-split + in-reg top-2 -------------
// warp = 16 tokens; loop 64 groups of 8 balls; no smem, no syncs.
__global__ void __launch_bounds__(256)
k4_top2() {
    int h = blockIdx.y;
    int tid = threadIdx.x;
    int wid = tid >> 5, lane = tid & 31;
    int tokw = blockIdx.x * 128 + wid * 16;
    int mrow = lane >> 2;          // 0..7
    int ep   = (lane & 3) * 2;     // e pair base

    const __nv_bfloat16* qs[3] = {g_q1, g_q2, g_q3};
    const __nv_bfloat16* ms[3] = {g_km1, g_km2, g_km3};

    // A fragments (loaded once): [split][kstep][4]
    uint32_t afr[3][2][4];
    #pragma unroll
    for (int s = 0; s < 3; s++) {
        const __nv_bfloat16* q = qs[s] + (h * NM + tokw) * EE;
        #pragma unroll
        for (int kk = 0; kk < 2; kk++) {
            int e = kk * 16 + ep;
            afr[s][kk][0] = *(const uint32_t*)(q + (mrow    ) * EE + e);
            afr[s][kk][1] = *(const uint32_t*)(q + (mrow + 8) * EE + e);
            afr[s][kk][2] = *(const uint32_t*)(q + (mrow    ) * EE + e + 8);
            afr[s][kk][3] = *(const uint32_t*)(q + (mrow + 8) * EE + e + 8);
        }
    }

    // top-2 state: row a = tokw+mrow, row b = tokw+8+mrow
    float v1a = -1e30f, v2a = -1e30f, v1b = -1e30f, v2b = -1e30f;
    int   i1a = 0, i2a = 0, i1b = 0, i2b = 0;

    for (int grp = 0; grp < 64; grp++) {
        int ball0 = grp * 8;
        uint32_t bfr[3][2][2];
        #pragma unroll
        for (int s = 0; s < 3; s++) {
            const __nv_bfloat16* m = ms[s] + (h * NB + ball0 + mrow) * EE;
            #pragma unroll
            for (int kk = 0; kk < 2; kk++) {
                int e = kk * 16 + ep;
                bfr[s][kk][0] = *(const uint32_t*)(m + e);
                bfr[s][kk][1] = *(const uint32_t*)(m + e + 8);
            }
        }
        float acc[4] = {0.f, 0.f, 0.f, 0.f};
        // 6 split-product pairs: (0,0)(0,1)(1,0)(1,1)(0,2)(2,0)
        #pragma unroll
        for (int kk = 0; kk < 2; kk++) {
            mma16816(acc, afr[0][kk], bfr[0][kk][0], bfr[0][kk][1]);
            mma16816(acc, afr[0][kk], bfr[1][kk][0], bfr[1][kk][1]);
            mma16816(acc, afr[1][kk], bfr[0][kk][0], bfr[0][kk][1]);
            mma16816(acc, afr[1][kk], bfr[1][kk][0], bfr[1][kk][1]);
            mma16816(acc, afr[0][kk], bfr[2][kk][0], bfr[2][kk][1]);
            mma16816(acc, afr[2][kk], bfr[0][kk][0], bfr[0][kk][1]);
        }

        int c0 = ball0 + ep, c1 = c0 + 1;
        if (acc[0] > v1a) { v2a = v1a; i2a = i1a; v1a = acc[0]; i1a = c0; }
        else if (acc[0] > v2a) { v2a = acc[0]; i2a = c0; }
        if (acc[1] > v1a) { v2a = v1a; i2a = i1a; v1a = acc[1]; i1a = c1; }
        else if (acc[1] > v2a) { v2a = acc[1]; i2a = c1; }
        if (acc[2] > v1b) { v2b = v1b; i2b = i1b; v1b = acc[2]; i1b = c0; }
        else if (acc[2] > v2b) { v2b = acc[2]; i2b = c0; }
        if (acc[3] > v1b) { v2b = v1b; i2b = i1b; v1b = acc[3]; i1b = c1; }
        else if (acc[3] > v2b) { v2b = acc[3]; i2b = c1; }
    }

    // merge top-2 across the 4 lanes of each row quad (others always hold
    // higher ball indices from the writing lane's perspective -> ties keep own)
    #pragma unroll
    for (int d = 1; d < 4; d <<= 1) {
        float o1 = __shfl_xor_sync(0xffffffffu, v1a, d);
        float o2 = __shfl_xor_sync(0xffffffffu, v2a, d);
        int  oi1 = __shfl_xor_sync(0xffffffffu, i1a, d);
        int  oi2 = __shfl_xor_sync(0xffffffffu, i2a, d);
        if (o1 > v1a) {
            if (v1a > o2) { v2a = v1a; i2a = i1a; } else { v2a = o2; i2a = oi2; }
            v1a = o1; i1a = oi1;
        } else if (o1 > v2a) { v2a = o1; i2a = oi1; }

        float p1 = __shfl_xor_sync(0xffffffffu, v1b, d);
        float p2 = __shfl_xor_sync(0xffffffffu, v2b, d);
        int  pi1 = __shfl_xor_sync(0xffffffffu, i1b, d);
        int  pi2 = __shfl_xor_sync(0xffffffffu, i2b, d);
        if (p1 > v1b) {
            if (v1b > p2) { v2b = v1b; i2b = i1b; } else { v2b = p2; i2b = pi2; }
            v1b = p1; i1b = pi1;
        } else if (p1 > v2b) { v2b = p1; i2b = pi1; }
    }
    if ((lane & 3) == 0) {
        int ta = h * NM + tokw + mrow;
        int tb = ta + 8;
        g_idx[ta * 2 + 0] = i1a; g_idx[ta * 2 + 1] = i2a;
        g_idx[tb * 2 + 0] = i1b; g_idx[tb * 2 + 1] = i2b;
    }
}

// ---------------- k5: gathered 32-key attention (fp16 V) + bf16 split out -----------
__global__ void k5_attn() {
    int warp = (blockIdx.x * blockDim.x + threadIdx.x) >> 5;
    int lane = threadIdx.x & 31;
    int h = warp >> 13;
    int tok = warp & (NM - 1);
    int b0 = g_idx[warp * 2 + 0];
    int b1 = g_idx[warp * 2 + 1];

    int ball = (lane < 16) ? b0 : b1;
    int ktok = ball * MB + (lane & 15);
    const float4* krow = (const float4*)(g_k + (h * NM + ktok) * EE);
    const float4* qrow = (const float4*)(g_q + (h * NM + tok) * EE);
    float logit = 0.f;
    #pragma unroll
    for (int e = 0; e < 8; e++) {
        float4 qv = qrow[e], kv = krow[e];
        logit += qv.x * kv.x + qv.y * kv.y + qv.z * kv.z + qv.w * kv.w;
    }
    logit *= 0.17677669529663688f;

    float m = logit;
    #pragma unroll
    for (int off = 16; off > 0; off >>= 1)
        m = fmaxf(m, __shfl_xor_sync(0xffffffffu, m, off));
    float p = __expf(logit - m);
    float s = p;
    #pragma unroll
    for (int off = 16; off > 0; off >>= 1)
        s += __shfl_xor_sync(0xffffffffu, s, off);
    float attn = p / s;

    float out = 0.f;
    #pragma unroll
    for (int kk = 0; kk < NKEY; kk++) {
        float a = __shfl_sync(0xffffffffu, attn, kk);
        int kt = ((kk < 16) ? b0 : b1) * MB + (kk & 15);
        out += a * __half2float(g_vh[(h * NM + kt) * EE + lane]);
    }
    int oi = tok * DIMM + h * EE + lane;
    __nv_bfloat16 hi = __float2bfloat16(out);
    g_aoh[oi] = hi;
    g_aol[oi] = __float2bfloat16(out - __bfloat162float(hi));
}

// ---------------- launch --------------------------------------------------------------
extern "C" void kernel_launch(void* const* d_in, const int* in_sizes, int n_in,
                              void* d_out, int out_size) {
    const float* x     = (const float*)d_in[0];
    const float* pos   = (const float*)d_in[1];
    const float* Wqkv  = (const float*)d_in[2];
    const float* bqkv  = (const float*)d_in[3];
    const float* Wpe   = (const float*)d_in[4];
    const float* bpe   = (const float*)d_in[5];
    const float* Wproj = (const float*)d_in[6];
    const float* bproj = (const float*)d_in[7];
    float* out = (float*)d_out;

    const int DSMEM = 2 * 65536 + 1024;
    cudaFuncSetAttribute(gemm_mma<0>, cudaFuncAttributeMaxDynamicSharedMemorySize, DSMEM);
    cudaFuncSetAttribute(gemm_mma<1>, cudaFuncAttributeMaxDynamicSharedMemorySize, DSMEM);

    kconv_w<<<1024, 256>>>(Wqkv, Wproj);
    k1_pe<<<NB, 256>>>(x, pos, Wpe, bpe);
    k2_qk<<<dim3(NM / 128, 512 / 128), 256>>>(bqkv);
    gemm_mma<0><<<dim3(NM / 128, 256 / 128), 256, DSMEM>>>(bqkv, nullptr);
    k3_kmean<<<(NH * NB * EE) / 256, 256>>>();
    k4_top2<<<dim3(NM / 128, NH), 256>>>();
    k5_attn<<<(NH * NM * 32) / 256, 256>>>();
    gemm_mma<1><<<dim3(NM / 128, DIMM / 128), 256, DSMEM>>>(bproj, out);
}

// round 11
// speedup vs baseline: 1.2803x; 1.1798x over previous
#include <cuda_runtime.h>
#include <cuda_bf16.h>
#include <cuda_fp16.h>
#include <cstdint>

#define NM   8192
#define DIMM 256
#define NH   8
#define EE   32
#define MB   16
#define NB   512
#define NKEY 32
#define NQKV 768

// ---------------- scratch ----------------------------------------------------
__device__ float g_xp[NM * DIMM];
__device__ __align__(16) __nv_bfloat16 g_xph[NM * DIMM];
__device__ __align__(16) __nv_bfloat16 g_xpl[NM * DIMM];
__device__ float g_wqk[512 * DIMM];
__device__ __align__(16) __nv_bfloat16 g_wvh[256 * DIMM];
__device__ __align__(16) __nv_bfloat16 g_wvl[256 * DIMM];
__device__ __align__(16) __nv_bfloat16 g_wph[DIMM * DIMM];
__device__ __align__(16) __nv_bfloat16 g_wpl[DIMM * DIMM];
__device__ __align__(16) __nv_bfloat16 g_aoh[NM * DIMM];
__device__ __align__(16) __nv_bfloat16 g_aol[NM * DIMM];
__device__ float g_q[NH * NM * EE];
__device__ float g_k[NH * NM * EE];              // fp32 K (selection path: kmean)
__device__ __align__(16) __half g_kh[NH * NM * EE];  // fp16 K (k5 logits)
__device__ __align__(16) __half g_vh[NH * NM * EE];  // fp16 V
__device__ int   g_idx[NH * NM * 2];
// 3-way bf16 splits for the selection GEMM (exact to ~2^-25)
__device__ __align__(16) __nv_bfloat16 g_q1[NH * NM * EE];
__device__ __align__(16) __nv_bfloat16 g_q2[NH * NM * EE];
__device__ __align__(16) __nv_bfloat16 g_q3[NH * NM * EE];
__device__ __align__(16) __nv_bfloat16 g_km1[NH * NB * EE];
__device__ __align__(16) __nv_bfloat16 g_km2[NH * NB * EE];
__device__ __align__(16) __nv_bfloat16 g_km3[NH * NB * EE];

// ---------------- packed f32x2 helpers ----------------------------------------
typedef unsigned long long ull;
__device__ __forceinline__ ull pack2(float x, float y) {
    ull r; asm("mov.b64 %0, {%1, %2};" : "=l"(r) : "f"(x), "f"(y)); return r;
}
__device__ __forceinline__ ull fma2(ull a, ull b, ull c) {
    ull d; asm("fma.rn.f32x2 %0, %1, %2, %3;" : "=l"(d) : "l"(a), "l"(b), "l"(c));
    return d;
}
__device__ __forceinline__ void unpack2(ull v, float& lo, float& hi) {
    asm("mov.b64 {%0, %1}, %2;" : "=f"(lo), "=f"(hi) : "l"(v));
}

// ---------------- mma.sync helpers ---------------------------------------------
__device__ __forceinline__ uint32_t smem_u32(const void* p) {
    uint32_t a;
    asm("{ .reg .u64 t; cvta.to.shared.u64 t, %1; cvt.u32.u64 %0, t; }" : "=r"(a) : "l"(p));
    return a;
}
__device__ __forceinline__ uint32_t swz_addr(uint32_t base, int r, int cb) {
    uint32_t off = (uint32_t)(r * 128 + cb);
    off ^= (off >> 3) & 0x70;
    return base + off;
}
__device__ __forceinline__ void ldsm4(uint32_t& r0, uint32_t& r1, uint32_t& r2,
                                      uint32_t& r3, uint32_t addr) {
    asm volatile("ldmatrix.sync.aligned.m8n8.x4.shared.b16 {%0,%1,%2,%3}, [%4];"
                 : "=r"(r0), "=r"(r1), "=r"(r2), "=r"(r3) : "r"(addr));
}
__device__ __forceinline__ void mma16816(float* d, const uint32_t* a,
                                         uint32_t b0, uint32_t b1) {
    asm volatile(
        "mma.sync.aligned.m16n8k16.row.col.f32.bf16.bf16.f32 "
        "{%0,%1,%2,%3}, {%4,%5,%6,%7}, {%8,%9}, {%0,%1,%2,%3};"
        : "+f"(d[0]), "+f"(d[1]), "+f"(d[2]), "+f"(d[3])
        : "r"(a[0]), "r"(a[1]), "r"(a[2]), "r"(a[3]), "r"(b0), "r"(b1));
}
__device__ __forceinline__ void cpasync16(uint32_t dst, const void* src) {
    asm volatile("cp.async.cg.shared.global [%0], [%1], 16;" :: "r"(dst), "l"(src));
}

// ---------------- k01: weight permutation/splits + PE add (merged) -----------------
__global__ void k01(const float* __restrict__ x, const float* __restrict__ pos,
                    const float* __restrict__ Wpe, const float* __restrict__ bpe,
                    const float* __restrict__ Wq, const float* __restrict__ Wp) {
    __shared__ float rel[MB][3];
    int tid = threadIdx.x;
    if (blockIdx.x < 1024) {
        int i = blockIdx.x * 256 + tid;
        if (i < NQKV * DIMM) {
            int c = i >> 8, d = i & 255;
            int h = c / 96, t = c % 96, e = t / 3, s = t - e * 3;
            float v = Wq[i];
            if (s < 2) {
                g_wqk[(h * 64 + e * 2 + s) * DIMM + d] = v;
            } else {
                __nv_bfloat16 hh = __float2bfloat16(v);
                int idx = (h * 32 + e) * DIMM + d;
                g_wvh[idx] = hh;
                g_wvl[idx] = __float2bfloat16(v - __bfloat162float(hh));
            }
        } else {
            int j = i - NQKV * DIMM;
            float v = Wp[j];
            __nv_bfloat16 hh = __float2bfloat16(v);
            g_wph[j] = hh;
            g_wpl[j] = __float2bfloat16(v - __bfloat162float(hh));
        }
        return;
    }
    int ball = blockIdx.x - 1024;
    if (tid < 3) {
        float s = 0.f;
        for (int m = 0; m < MB; m++) s += pos[(ball * MB + m) * 3 + tid];
        float mean = s * (1.f / MB);
        for (int m = 0; m < MB; m++)
            rel[m][tid] = pos[(ball * MB + m) * 3 + tid] - mean;
    }
    __syncthreads();
    int d = tid;
    float w0 = Wpe[d * 3 + 0], w1 = Wpe[d * 3 + 1], w2 = Wpe[d * 3 + 2];
    float b  = bpe[d];
    #pragma unroll
    for (int m = 0; m < MB; m++) {
        int t = ball * MB + m;
        float v = x[t * DIMM + d]
                + rel[m][0] * w0 + rel[m][1] * w1 + rel[m][2] * w2 + b;
        g_xp[t * DIMM + d] = v;
        __nv_bfloat16 h = __float2bfloat16(v);
        g_xph[t * DIMM + d] = h;
        g_xpl[t * DIMM + d] = __float2bfloat16(v - __bfloat162float(h));
    }
}

// ---------------- fp32 f32x2 GEMM-NT for Q,K (N=512), reg-prefetch pipelined ------
__global__ void __launch_bounds__(256, 2)
k2_qk(const float* __restrict__ bias) {
    __shared__ float As[2][16 * 132];
    __shared__ float Bs[2][16 * 132];
    int tid = threadIdx.x;
    int tx = tid & 15, ty = tid >> 4;
    int row0 = blockIdx.x * 128, col0 = blockIdx.y * 128;
    int r  = tid & 127;
    int k8 = (tid >> 7) * 8;

    const float* Ap = g_xp  + (row0 + r) * DIMM + k8;
    const float* Bp = g_wqk + (col0 + r) * DIMM + k8;

    float4 pa0 = *(const float4*)(Ap);
    float4 pa1 = *(const float4*)(Ap + 4);
    float4 pb0 = *(const float4*)(Bp);
    float4 pb1 = *(const float4*)(Bp + 4);

    ull accp[8][4] = {};
    #pragma unroll 2
    for (int c = 0; c < 16; c++) {
        float* A = As[c & 1];
        float* B = Bs[c & 1];
        A[(k8 + 0) * 132 + r] = pa0.x; A[(k8 + 1) * 132 + r] = pa0.y;
        A[(k8 + 2) * 132 + r] = pa0.z; A[(k8 + 3) * 132 + r] = pa0.w;
        A[(k8 + 4) * 132 + r] = pa1.x; A[(k8 + 5) * 132 + r] = pa1.y;
        A[(k8 + 6) * 132 + r] = pa1.z; A[(k8 + 7) * 132 + r] = pa1.w;
        B[(k8 + 0) * 132 + r] = pb0.x; B[(k8 + 1) * 132 + r] = pb0.y;
        B[(k8 + 2) * 132 + r] = pb0.z; B[(k8 + 3) * 132 + r] = pb0.w;
        B[(k8 + 4) * 132 + r] = pb1.x; B[(k8 + 5) * 132 + r] = pb1.y;
        B[(k8 + 6) * 132 + r] = pb1.z; B[(k8 + 7) * 132 + r] = pb1.w;
        __syncthreads();
        if (c < 15) {
            int k0n = (c + 1) * 16;
            pa0 = *(const float4*)(Ap + k0n);
            pa1 = *(const float4*)(Ap + k0n + 4);
            pb0 = *(const float4*)(Bp + k0n);
            pb1 = *(const float4*)(Bp + k0n + 4);
        }
        #pragma unroll
        for (int kk = 0; kk < 16; kk++) {
            float4 a0 = *(const float4*)(A + kk * 132 + ty * 4);
            float4 a1 = *(const float4*)(A + kk * 132 + 64 + ty * 4);
            float4 b0 = *(const float4*)(B + kk * 132 + tx * 4);
            float4 b1 = *(const float4*)(B + kk * 132 + 64 + tx * 4);
            ull bp[4] = {pack2(b0.x, b0.y), pack2(b0.z, b0.w),
                         pack2(b1.x, b1.y), pack2(b1.z, b1.w)};
            float av[8] = {a0.x, a0.y, a0.z, a0.w, a1.x, a1.y, a1.z, a1.w};
            #pragma unroll
            for (int i = 0; i < 8; i++) {
                ull ap = pack2(av[i], av[i]);
                #pragma unroll
                for (int j = 0; j < 4; j++) accp[i][j] = fma2(ap, bp[j], accp[i][j]);
            }
        }
    }
    float acc[8][8];
    #pragma unroll
    for (int i = 0; i < 8; i++)
        #pragma unroll
        for (int j = 0; j < 4; j++)
            unpack2(accp[i][j], acc[i][2 * j], acc[i][2 * j + 1]);
    #pragma unroll
    for (int i = 0; i < 8; i++) {
        int rr = row0 + ((i < 4) ? ty * 4 + i : 64 + ty * 4 + i - 4);
        #pragma unroll
        for (int j = 0; j < 8; j++) {
            int cp = col0 + ((j < 4) ? tx * 4 + j : 64 + tx * 4 + j - 4);
            int h = cp >> 6, r6 = cp & 63;
            int e = r6 >> 1, s = r6 & 1;
            float v = acc[i][j] + bias[h * 96 + e * 3 + s];
            int qi = (h * NM + rr) * EE + e;
            if (s == 0) {
                g_q[qi] = v;
                __nv_bfloat16 b1 = __float2bfloat16(v);
                float f1 = __bfloat162float(b1);
                __nv_bfloat16 b2 = __float2bfloat16(v - f1);
                float f2 = __bfloat162float(b2);
                __nv_bfloat16 b3 = __float2bfloat16(v - f1 - f2);
                g_q1[qi] = b1; g_q2[qi] = b2; g_q3[qi] = b3;
            } else {
                g_k[qi] = v;
                g_kh[qi] = __float2half(v);
            }
        }
    }
}

// ---------------- split-bf16 HMMA GEMM-NT, cp.async pipelined ----------------------
template<int MODE>
__device__ __forceinline__ void issue_chunk(uint32_t stage, int row0, int col0,
                                            int k0, int tid) {
    const __nv_bfloat16* srcs[4] = {
        (MODE == 0) ? g_xph : g_aoh, (MODE == 0) ? g_xpl : g_aol,
        (MODE == 0) ? g_wvh : g_wph, (MODE == 0) ? g_wvl : g_wpl};
    #pragma unroll
    for (int b = 0; b < 4; b++) {
        int rbase = (b < 2) ? row0 : col0;
        #pragma unroll
        for (int l = 0; l < 4; l++) {
            int u = tid + l * 256;
            int r = u >> 3, cc = u & 7;
            const void* g = srcs[b] + (rbase + r) * DIMM + k0 + cc * 8;
            uint32_t off = (uint32_t)(r * 128 + cc * 16);
            off ^= (off >> 3) & 0x70;
            cpasync16(stage + b * 16384 + off, g);
        }
    }
    asm volatile("cp.async.commit_group;" ::: "memory");
}

template<int MODE>
__global__ void __launch_bounds__(256, 1)
gemm_mma(const float* __restrict__ bias, float* __restrict__ out) {
    extern __shared__ char dsm_raw[];
    int tid = threadIdx.x;
    int wid = tid >> 5, lane = tid & 31;
    int row0 = blockIdx.x * 128, col0 = blockIdx.y * 128;
    int warp_m = (wid & 1) * 64;
    int warp_n = (wid >> 1) * 32;

    uint32_t raw = smem_u32(dsm_raw);
    uint32_t sbase = (raw + 1023u) & ~1023u;

    float acc[4][4][4] = {};
    int lr = lane & 7;
    int g  = lane >> 3;

    issue_chunk<MODE>(sbase, row0, col0, 0, tid);

    for (int chunk = 0; chunk < 4; chunk++) {
        if (chunk < 3)
            issue_chunk<MODE>(sbase + ((chunk + 1) & 1) * 65536,
                              row0, col0, (chunk + 1) * 64, tid);
        if (chunk < 3)
            asm volatile("cp.async.wait_group 1;" ::: "memory");
        else
            asm volatile("cp.async.wait_group 0;" ::: "memory");
        __syncthreads();

        uint32_t st = sbase + (chunk & 1) * 65536;
        uint32_t aBuf[2] = {st, st + 16384};
        uint32_t bBuf[2] = {st + 32768, st + 49152};

        #pragma unroll
        for (int pass = 0; pass < 3; pass++) {
            uint32_t abase = aBuf[(pass == 2) ? 1 : 0];
            uint32_t bbase = bBuf[(pass == 1) ? 1 : 0];
            #pragma unroll
            for (int ks = 0; ks < 4; ks++) {
                uint32_t af[4][4];
                #pragma unroll
                for (int mi = 0; mi < 4; mi++) {
                    int row = warp_m + mi * 16 + ((g & 1) << 3) + lr;
                    int cb  = ks * 32 + ((g >> 1) << 4);
                    ldsm4(af[mi][0], af[mi][1], af[mi][2], af[mi][3],
                          swz_addr(abase, row, cb));
                }
                uint32_t bf[4][2];
                #pragma unroll
                for (int p = 0; p < 2; p++) {
                    int n  = warp_n + p * 16 + ((g >> 1) << 3) + lr;
                    int cb = ks * 32 + ((g & 1) << 4);
                    uint32_t r0, r1, r2, r3;
                    ldsm4(r0, r1, r2, r3, swz_addr(bbase, n, cb));
                    bf[p * 2 + 0][0] = r0; bf[p * 2 + 0][1] = r1;
                    bf[p * 2 + 1][0] = r2; bf[p * 2 + 1][1] = r3;
                }
                #pragma unroll
                for (int mi = 0; mi < 4; mi++)
                    #pragma unroll
                    for (int nj = 0; nj < 4; nj++)
                        mma16816(acc[mi][nj], af[mi], bf[nj][0], bf[nj][1]);
            }
        }
        __syncthreads();
    }

    int erow = lane >> 2;
    int ecol = (lane & 3) * 2;
    #pragma unroll
    for (int mi = 0; mi < 4; mi++) {
        #pragma unroll
        for (int nj = 0; nj < 4; nj++) {
            #pragma unroll
            for (int half = 0; half < 2; half++) {
                int r = row0 + warp_m + mi * 16 + erow + half * 8;
                #pragma unroll
                for (int rg = 0; rg < 2; rg++) {
                    int cp = col0 + warp_n + nj * 8 + ecol + rg;
                    if (MODE == 0) {
                        int h = cp >> 5, e = cp & 31;
                        float v = acc[mi][nj][half * 2 + rg] + bias[h * 96 + e * 3 + 2];
                        g_vh[(h * NM + r) * EE + e] = __float2half(v);
                    } else {
                        float v = acc[mi][nj][half * 2 + rg] + bias[cp];
                        out[r * DIMM + cp] = v;
                    }
                }
            }
        }
    }
}

// ---------------- k3: per-ball key means -> 3-way bf16 splits ------------------------
__global__ void k3_kmean() {
    int t = blockIdx.x * blockDim.x + threadIdx.x;
    int e = t & 31;
    int ball = (t >> 5) & (NB - 1);
    int h = t >> 14;
    const float* base = g_k + (h * NM + ball * MB) * EE + e;
    float s = 0.f;
    #pragma unroll
    for (int m = 0; m < MB; m++) s += base[m * EE];
    float v = s * (1.f / MB);
    __nv_bfloat16 b1 = __float2bfloat16(v);
    float f1 = __bfloat162float(b1);
    __nv_bfloat16 b2 = __float2bfloat16(v - f1);
    float f2 = __bfloat162float(b2);
    __nv_bfloat16 b3 = __float2bfloat16(v - f1 - f2);
    g_km1[t] = b1; g_km2[t] = b2; g_km3[t] = b3;
}

// ---------------- k4: sim via HMMA 6-product split, dual-acc + B prefetch -----------
__device__ __forceinline__ void k4_load_b(uint32_t bfr[3][2][2], int h, int ball0,
                                          int mrow, int ep) {
    const __nv_bfloat16* ms[3] = {g_km1, g_km2, g_km3};
    #pragma unroll
    for (int s = 0; s < 3; s++) {
        const __nv_bfloat16* m = ms[s] + (h * NB + ball0 + mrow) * EE;
        #pragma unroll
        for (int kk = 0; kk < 2; kk++) {
            int e = kk * 16 + ep;
            bfr[s][kk][0] = *(const uint32_t*)(m + e);
            bfr[s][kk][1] = *(const uint32_t*)(m + e + 8);
        }
    }
}

__global__ void __launch_bounds__(256)
k4_top2() {
    int h = blockIdx.y;
    int tid = threadIdx.x;
    int wid = tid >> 5, lane = tid & 31;
    int tokw = blockIdx.x * 128 + wid * 16;
    int mrow = lane >> 2;
    int ep   = (lane & 3) * 2;

    const __nv_bfloat16* qs[3] = {g_q1, g_q2, g_q3};

    uint32_t afr[3][2][4];
    #pragma unroll
    for (int s = 0; s < 3; s++) {
        const __nv_bfloat16* q = qs[s] + (h * NM + tokw) * EE;
        #pragma unroll
        for (int kk = 0; kk < 2; kk++) {
            int e = kk * 16 + ep;
            afr[s][kk][0] = *(const uint32_t*)(q + (mrow    ) * EE + e);
            afr[s][kk][1] = *(const uint32_t*)(q + (mrow + 8) * EE + e);
            afr[s][kk][2] = *(const uint32_t*)(q + (mrow    ) * EE + e + 8);
            afr[s][kk][3] = *(const uint32_t*)(q + (mrow + 8) * EE + e + 8);
        }
    }

    float v1a = -1e30f, v2a = -1e30f, v1b = -1e30f, v2b = -1e30f;
    int   i1a = 0, i2a = 0, i1b = 0, i2b = 0;

    uint32_t bf[2][3][2][2];
    k4_load_b(bf[0], h, 0, mrow, ep);

    #pragma unroll 2
    for (int grp = 0; grp < 64; grp++) {
        int cur = grp & 1;
        int ball0 = grp * 8;
        if (grp < 63)
            k4_load_b(bf[cur ^ 1], h, ball0 + 8, mrow, ep);

        // two independent accumulator chains (3 products each), summed after
        float acc[4] = {0.f, 0.f, 0.f, 0.f};
        float acd[4] = {0.f, 0.f, 0.f, 0.f};
        #pragma unroll
        for (int kk = 0; kk < 2; kk++) {
            mma16816(acc, afr[0][kk], bf[cur][0][kk][0], bf[cur][0][kk][1]); // 11
            mma16816(acd, afr[0][kk], bf[cur][1][kk][0], bf[cur][1][kk][1]); // 12
            mma16816(acc, afr[1][kk], bf[cur][0][kk][0], bf[cur][0][kk][1]); // 21
            mma16816(acd, afr[1][kk], bf[cur][1][kk][0], bf[cur][1][kk][1]); // 22
            mma16816(acc, afr[0][kk], bf[cur][2][kk][0], bf[cur][2][kk][1]); // 13
            mma16816(acd, afr[2][kk], bf[cur][0][kk][0], bf[cur][0][kk][1]); // 31
        }
        #pragma unroll
        for (int i = 0; i < 4; i++) acc[i] += acd[i];

        int c0 = ball0 + ep, c1 = c0 + 1;
        if (acc[0] > v1a) { v2a = v1a; i2a = i1a; v1a = acc[0]; i1a = c0; }
        else if (acc[0] > v2a) { v2a = acc[0]; i2a = c0; }
        if (acc[1] > v1a) { v2a = v1a; i2a = i1a; v1a = acc[1]; i1a = c1; }
        else if (acc[1] > v2a) { v2a = acc[1]; i2a = c1; }
        if (acc[2] > v1b) { v2b = v1b; i2b = i1b; v1b = acc[2]; i1b = c0; }
        else if (acc[2] > v2b) { v2b = acc[2]; i2b = c0; }
        if (acc[3] > v1b) { v2b = v1b; i2b = i1b; v1b = acc[3]; i1b = c1; }
        else if (acc[3] > v2b) { v2b = acc[3]; i2b = c1; }
    }

    #pragma unroll
    for (int d = 1; d < 4; d <<= 1) {
        float o1 = __shfl_xor_sync(0xffffffffu, v1a, d);
        float o2 = __shfl_xor_sync(0xffffffffu, v2a, d);
        int  oi1 = __shfl_xor_sync(0xffffffffu, i1a, d);
        int  oi2 = __shfl_xor_sync(0xffffffffu, i2a, d);
        if (o1 > v1a) {
            if (v1a > o2) { v2a = v1a; i2a = i1a; } else { v2a = o2; i2a = oi2; }
            v1a = o1; i1a = oi1;
        } else if (o1 > v2a) { v2a = o1; i2a = oi1; }

        float p1 = __shfl_xor_sync(0xffffffffu, v1b, d);
        float p2 = __shfl_xor_sync(0xffffffffu, v2b, d);
        int  pi1 = __shfl_xor_sync(0xffffffffu, i1b, d);
        int  pi2 = __shfl_xor_sync(0xffffffffu, i2b, d);
        if (p1 > v1b) {
            if (v1b > p2) { v2b = v1b; i2b = i1b; } else { v2b = p2; i2b = pi2; }
            v1b = p1; i1b = pi1;
        } else if (p1 > v2b) { v2b = p1; i2b = pi1; }
    }
    if ((lane & 3) == 0) {
        int ta = h * NM + tokw + mrow;
        int tb = ta + 8;
        g_idx[ta * 2 + 0] = i1a; g_idx[ta * 2 + 1] = i2a;
        g_idx[tb * 2 + 0] = i1b; g_idx[tb * 2 + 1] = i2b;
    }
}

// ---------------- k5: gathered 32-key attention (fp16 K,V) + bf16 split out ---------
__global__ void k5_attn() {
    int warp = (blockIdx.x * blockDim.x + threadIdx.x) >> 5;
    int lane = threadIdx.x & 31;
    int h = warp >> 13;
    int tok = warp & (NM - 1);
    int b0 = g_idx[warp * 2 + 0];
    int b1 = g_idx[warp * 2 + 1];

    int ball = (lane < 16) ? b0 : b1;
    int ktok = ball * MB + (lane & 15);
    const uint4*  kr4  = (const uint4*)(g_kh + (h * NM + ktok) * EE);
    const float4* qrow = (const float4*)(g_q + (h * NM + tok) * EE);
    float logit = 0.f;
    #pragma unroll
    for (int i = 0; i < 4; i++) {
        uint4 u = kr4[i];
        float4 qa = qrow[2 * i], qb = qrow[2 * i + 1];
        float2 k0 = __half22float2(*(__half2*)&u.x);
        float2 k1 = __half22float2(*(__half2*)&u.y);
        float2 k2 = __half22float2(*(__half2*)&u.z);
        float2 k3 = __half22float2(*(__half2*)&u.w);
        logit += qa.x * k0.x + qa.y * k0.y + qa.z * k1.x + qa.w * k1.y
               + qb.x * k2.x + qb.y * k2.y + qb.z * k3.x + qb.w * k3.y;
    }
    logit *= 0.17677669529663688f;

    float m = logit;
    #pragma unroll
    for (int off = 16; off > 0; off >>= 1)
        m = fmaxf(m, __shfl_xor_sync(0xffffffffu, m, off));
    float p = __expf(logit - m);
    float s = p;
    #pragma unroll
    for (int off = 16; off > 0; off >>= 1)
        s += __shfl_xor_sync(0xffffffffu, s, off);
    float attn = p / s;

    float out = 0.f;
    #pragma unroll
    for (int kk = 0; kk < NKEY; kk++) {
        float a = __shfl_sync(0xffffffffu, attn, kk);
        int kt = ((kk < 16) ? b0 : b1) * MB + (kk & 15);
        out += a * __half2float(g_vh[(h * NM + kt) * EE + lane]);
    }
    int oi = tok * DIMM + h * EE + lane;
    __nv_bfloat16 hi = __float2bfloat16(out);
    g_aoh[oi] = hi;
    g_aol[oi] = __float2bfloat16(out - __bfloat162float(hi));
}

// ---------------- launch --------------------------------------------------------------
extern "C" void kernel_launch(void* const* d_in, const int* in_sizes, int n_in,
                              void* d_out, int out_size) {
    const float* x     = (const float*)d_in[0];
    const float* pos   = (const float*)d_in[1];
    const float* Wqkv  = (const float*)d_in[2];
    const float* bqkv  = (const float*)d_in[3];
    const float* Wpe   = (const float*)d_in[4];
    const float* bpe   = (const float*)d_in[5];
    const float* Wproj = (const float*)d_in[6];
    const float* bproj = (const float*)d_in[7];
    float* out = (float*)d_out;

    const int DSMEM = 2 * 65536 + 1024;
    cudaFuncSetAttribute(gemm_mma<0>, cudaFuncAttributeMaxDynamicSharedMemorySize, DSMEM);
    cudaFuncSetAttribute(gemm_mma<1>, cudaFuncAttributeMaxDynamicSharedMemorySize, DSMEM);

    k01<<<1024 + NB, 256>>>(x, pos, Wpe, bpe, Wqkv, Wproj);
    k2_qk<<<dim3(NM / 128, 512 / 128), 256>>>(bqkv);
    gemm_mma<0><<<dim3(NM / 128, 256 / 128), 256, DSMEM>>>(bqkv, nullptr);
    k3_kmean<<<(NH * NB * EE) / 256, 256>>>();
    k4_top2<<<dim3(NM / 128, NH), 256>>>();
    k5_attn<<<(NH * NM * 32) / 256, 256>>>();
    gemm_mma<1><<<dim3(NM / 128, DIMM / 128), 256, DSMEM>>>(bproj, out);
}

// round 12
// speedup vs baseline: 1.3161x; 1.0279x over previous
#include <cuda_runtime.h>
#include <cuda_bf16.h>
#include <cuda_fp16.h>
#include <cstdint>

#define NM   8192
#define DIMM 256
#define NH   8
#define EE   32
#define MB   16
#define NB   512
#define NKEY 32
#define NQKV 768

// ---------------- scratch ----------------------------------------------------
__device__ float g_xp[NM * DIMM];
__device__ __align__(16) __nv_bfloat16 g_xph[NM * DIMM];
__device__ __align__(16) __nv_bfloat16 g_xpl[NM * DIMM];
__device__ float g_wqk[512 * DIMM];
__device__ __align__(16) __nv_bfloat16 g_wvh[256 * DIMM];
__device__ __align__(16) __nv_bfloat16 g_wvl[256 * DIMM];
__device__ __align__(16) __nv_bfloat16 g_wph[DIMM * DIMM];
__device__ __align__(16) __nv_bfloat16 g_wpl[DIMM * DIMM];
__device__ __align__(16) __nv_bfloat16 g_aoh[NM * DIMM];
__device__ __align__(16) __nv_bfloat16 g_aol[NM * DIMM];
__device__ float g_q[NH * NM * EE];
__device__ float g_k[NH * NM * EE];              // fp32 K (selection path: kmean)
__device__ __align__(16) __half g_kh[NH * NM * EE];  // fp16 K (k5 logits)
__device__ __align__(16) __half g_vh[NH * NM * EE];  // fp16 V
__device__ int   g_idx[NH * NM * 2];
// 3-way bf16 splits for the selection GEMM (exact to ~2^-25)
__device__ __align__(16) __nv_bfloat16 g_q1[NH * NM * EE];
__device__ __align__(16) __nv_bfloat16 g_q2[NH * NM * EE];
__device__ __align__(16) __nv_bfloat16 g_q3[NH * NM * EE];
__device__ __align__(16) __nv_bfloat16 g_km1[NH * NB * EE];
__device__ __align__(16) __nv_bfloat16 g_km2[NH * NB * EE];
__device__ __align__(16) __nv_bfloat16 g_km3[NH * NB * EE];

// ---------------- packed f32x2 helpers ----------------------------------------
typedef unsigned long long ull;
__device__ __forceinline__ ull pack2(float x, float y) {
    ull r; asm("mov.b64 %0, {%1, %2};" : "=l"(r) : "f"(x), "f"(y)); return r;
}
__device__ __forceinline__ ull fma2(ull a, ull b, ull c) {
    ull d; asm("fma.rn.f32x2 %0, %1, %2, %3;" : "=l"(d) : "l"(a), "l"(b), "l"(c));
    return d;
}
__device__ __forceinline__ void unpack2(ull v, float& lo, float& hi) {
    asm("mov.b64 {%0, %1}, %2;" : "=f"(lo), "=f"(hi) : "l"(v));
}

// ---------------- mma.sync helpers ---------------------------------------------
__device__ __forceinline__ uint32_t smem_u32(const void* p) {
    uint32_t a;
    asm("{ .reg .u64 t; cvta.to.shared.u64 t, %1; cvt.u32.u64 %0, t; }" : "=r"(a) : "l"(p));
    return a;
}
__device__ __forceinline__ uint32_t swz_addr(uint32_t base, int r, int cb) {
    uint32_t off = (uint32_t)(r * 128 + cb);
    off ^= (off >> 3) & 0x70;
    return base + off;
}
__device__ __forceinline__ void ldsm4(uint32_t& r0, uint32_t& r1, uint32_t& r2,
                                      uint32_t& r3, uint32_t addr) {
    asm volatile("ldmatrix.sync.aligned.m8n8.x4.shared.b16 {%0,%1,%2,%3}, [%4];"
                 : "=r"(r0), "=r"(r1), "=r"(r2), "=r"(r3) : "r"(addr));
}
__device__ __forceinline__ void mma16816(float* d, const uint32_t* a,
                                         uint32_t b0, uint32_t b1) {
    asm volatile(
        "mma.sync.aligned.m16n8k16.row.col.f32.bf16.bf16.f32 "
        "{%0,%1,%2,%3}, {%4,%5,%6,%7}, {%8,%9}, {%0,%1,%2,%3};"
        : "+f"(d[0]), "+f"(d[1]), "+f"(d[2]), "+f"(d[3])
        : "r"(a[0]), "r"(a[1]), "r"(a[2]), "r"(a[3]), "r"(b0), "r"(b1));
}
__device__ __forceinline__ void cpasync16(uint32_t dst, const void* src) {
    asm volatile("cp.async.cg.shared.global [%0], [%1], 16;" :: "r"(dst), "l"(src));
}

// ---------------- k01: weight permutation/splits + PE add (merged) -----------------
__global__ void k01(const float* __restrict__ x, const float* __restrict__ pos,
                    const float* __restrict__ Wpe, const float* __restrict__ bpe,
                    const float* __restrict__ Wq, const float* __restrict__ Wp) {
    __shared__ float rel[MB][3];
    int tid = threadIdx.x;
    if (blockIdx.x < 1024) {
        int i = blockIdx.x * 256 + tid;
        if (i < NQKV * DIMM) {
            int c = i >> 8, d = i & 255;
            int h = c / 96, t = c % 96, e = t / 3, s = t - e * 3;
            float v = Wq[i];
            if (s < 2) {
                g_wqk[(h * 64 + e * 2 + s) * DIMM + d] = v;
            } else {
                __nv_bfloat16 hh = __float2bfloat16(v);
                int idx = (h * 32 + e) * DIMM + d;
                g_wvh[idx] = hh;
                g_wvl[idx] = __float2bfloat16(v - __bfloat162float(hh));
            }
        } else {
            int j = i - NQKV * DIMM;
            float v = Wp[j];
            __nv_bfloat16 hh = __float2bfloat16(v);
            g_wph[j] = hh;
            g_wpl[j] = __float2bfloat16(v - __bfloat162float(hh));
        }
        return;
    }
    int ball = blockIdx.x - 1024;
    if (tid < 3) {
        float s = 0.f;
        for (int m = 0; m < MB; m++) s += pos[(ball * MB + m) * 3 + tid];
        float mean = s * (1.f / MB);
        for (int m = 0; m < MB; m++)
            rel[m][tid] = pos[(ball * MB + m) * 3 + tid] - mean;
    }
    __syncthreads();
    int d = tid;
    float w0 = Wpe[d * 3 + 0], w1 = Wpe[d * 3 + 1], w2 = Wpe[d * 3 + 2];
    float b  = bpe[d];
    #pragma unroll
    for (int m = 0; m < MB; m++) {
        int t = ball * MB + m;
        float v = x[t * DIMM + d]
                + rel[m][0] * w0 + rel[m][1] * w1 + rel[m][2] * w2 + b;
        g_xp[t * DIMM + d] = v;
        __nv_bfloat16 h = __float2bfloat16(v);
        g_xph[t * DIMM + d] = h;
        g_xpl[t * DIMM + d] = __float2bfloat16(v - __bfloat162float(h));
    }
}

// ---------------- fp32 f32x2 GEMM-NT for Q,K (N=512), reg-prefetch pipelined ------
__global__ void __launch_bounds__(256, 2)
k2_qk(const float* __restrict__ bias) {
    __shared__ float As[2][16 * 132];
    __shared__ float Bs[2][16 * 132];
    int tid = threadIdx.x;
    int tx = tid & 15, ty = tid >> 4;
    int row0 = blockIdx.x * 128, col0 = blockIdx.y * 128;
    int r  = tid & 127;
    int k8 = (tid >> 7) * 8;

    const float* Ap = g_xp  + (row0 + r) * DIMM + k8;
    const float* Bp = g_wqk + (col0 + r) * DIMM + k8;

    float4 pa0 = *(const float4*)(Ap);
    float4 pa1 = *(const float4*)(Ap + 4);
    float4 pb0 = *(const float4*)(Bp);
    float4 pb1 = *(const float4*)(Bp + 4);

    ull accp[8][4] = {};
    #pragma unroll 2
    for (int c = 0; c < 16; c++) {
        float* A = As[c & 1];
        float* B = Bs[c & 1];
        A[(k8 + 0) * 132 + r] = pa0.x; A[(k8 + 1) * 132 + r] = pa0.y;
        A[(k8 + 2) * 132 + r] = pa0.z; A[(k8 + 3) * 132 + r] = pa0.w;
        A[(k8 + 4) * 132 + r] = pa1.x; A[(k8 + 5) * 132 + r] = pa1.y;
        A[(k8 + 6) * 132 + r] = pa1.z; A[(k8 + 7) * 132 + r] = pa1.w;
        B[(k8 + 0) * 132 + r] = pb0.x; B[(k8 + 1) * 132 + r] = pb0.y;
        B[(k8 + 2) * 132 + r] = pb0.z; B[(k8 + 3) * 132 + r] = pb0.w;
        B[(k8 + 4) * 132 + r] = pb1.x; B[(k8 + 5) * 132 + r] = pb1.y;
        B[(k8 + 6) * 132 + r] = pb1.z; B[(k8 + 7) * 132 + r] = pb1.w;
        __syncthreads();
        if (c < 15) {
            int k0n = (c + 1) * 16;
            pa0 = *(const float4*)(Ap + k0n);
            pa1 = *(const float4*)(Ap + k0n + 4);
            pb0 = *(const float4*)(Bp + k0n);
            pb1 = *(const float4*)(Bp + k0n + 4);
        }
        #pragma unroll
        for (int kk = 0; kk < 16; kk++) {
            float4 a0 = *(const float4*)(A + kk * 132 + ty * 4);
            float4 a1 = *(const float4*)(A + kk * 132 + 64 + ty * 4);
            float4 b0 = *(const float4*)(B + kk * 132 + tx * 4);
            float4 b1 = *(const float4*)(B + kk * 132 + 64 + tx * 4);
            ull bp[4] = {pack2(b0.x, b0.y), pack2(b0.z, b0.w),
                         pack2(b1.x, b1.y), pack2(b1.z, b1.w)};
            float av[8] = {a0.x, a0.y, a0.z, a0.w, a1.x, a1.y, a1.z, a1.w};
            #pragma unroll
            for (int i = 0; i < 8; i++) {
                ull ap = pack2(av[i], av[i]);
                #pragma unroll
                for (int j = 0; j < 4; j++) accp[i][j] = fma2(ap, bp[j], accp[i][j]);
            }
        }
    }
    float acc[8][8];
    #pragma unroll
    for (int i = 0; i < 8; i++)
        #pragma unroll
        for (int j = 0; j < 4; j++)
            unpack2(accp[i][j], acc[i][2 * j], acc[i][2 * j + 1]);
    #pragma unroll
    for (int i = 0; i < 8; i++) {
        int rr = row0 + ((i < 4) ? ty * 4 + i : 64 + ty * 4 + i - 4);
        #pragma unroll
        for (int j = 0; j < 8; j++) {
            int cp = col0 + ((j < 4) ? tx * 4 + j : 64 + tx * 4 + j - 4);
            int h = cp >> 6, r6 = cp & 63;
            int e = r6 >> 1, s = r6 & 1;
            float v = acc[i][j] + bias[h * 96 + e * 3 + s];
            int qi = (h * NM + rr) * EE + e;
            if (s == 0) {
                g_q[qi] = v;
                __nv_bfloat16 b1 = __float2bfloat16(v);
                float f1 = __bfloat162float(b1);
                __nv_bfloat16 b2 = __float2bfloat16(v - f1);
                float f2 = __bfloat162float(b2);
                __nv_bfloat16 b3 = __float2bfloat16(v - f1 - f2);
                g_q1[qi] = b1; g_q2[qi] = b2; g_q3[qi] = b3;
            } else {
                g_k[qi] = v;
                g_kh[qi] = __float2half(v);
            }
        }
    }
}

// ---------------- split-bf16 HMMA GEMM-NT, cp.async pipelined ----------------------
template<int MODE>
__device__ __forceinline__ void issue_chunk(uint32_t stage, int row0, int col0,
                                            int k0, int tid) {
    const __nv_bfloat16* srcs[4] = {
        (MODE == 0) ? g_xph : g_aoh, (MODE == 0) ? g_xpl : g_aol,
        (MODE == 0) ? g_wvh : g_wph, (MODE == 0) ? g_wvl : g_wpl};
    #pragma unroll
    for (int b = 0; b < 4; b++) {
        int rbase = (b < 2) ? row0 : col0;
        #pragma unroll
        for (int l = 0; l < 4; l++) {
            int u = tid + l * 256;
            int r = u >> 3, cc = u & 7;
            const void* g = srcs[b] + (rbase + r) * DIMM + k0 + cc * 8;
            uint32_t off = (uint32_t)(r * 128 + cc * 16);
            off ^= (off >> 3) & 0x70;
            cpasync16(stage + b * 16384 + off, g);
        }
    }
    asm volatile("cp.async.commit_group;" ::: "memory");
}

template<int MODE>
__global__ void __launch_bounds__(256, 1)
gemm_mma(const float* __restrict__ bias, float* __restrict__ out) {
    extern __shared__ char dsm_raw[];
    int tid = threadIdx.x;
    int wid = tid >> 5, lane = tid & 31;
    int row0 = blockIdx.x * 128, col0 = blockIdx.y * 128;
    int warp_m = (wid & 1) * 64;
    int warp_n = (wid >> 1) * 32;

    uint32_t raw = smem_u32(dsm_raw);
    uint32_t sbase = (raw + 1023u) & ~1023u;

    float acc[4][4][4] = {};
    int lr = lane & 7;
    int g  = lane >> 3;

    issue_chunk<MODE>(sbase, row0, col0, 0, tid);

    for (int chunk = 0; chunk < 4; chunk++) {
        if (chunk < 3)
            issue_chunk<MODE>(sbase + ((chunk + 1) & 1) * 65536,
                              row0, col0, (chunk + 1) * 64, tid);
        if (chunk < 3)
            asm volatile("cp.async.wait_group 1;" ::: "memory");
        else
            asm volatile("cp.async.wait_group 0;" ::: "memory");
        __syncthreads();

        uint32_t st = sbase + (chunk & 1) * 65536;
        uint32_t aBuf[2] = {st, st + 16384};
        uint32_t bBuf[2] = {st + 32768, st + 49152};

        #pragma unroll
        for (int pass = 0; pass < 3; pass++) {
            uint32_t abase = aBuf[(pass == 2) ? 1 : 0];
            uint32_t bbase = bBuf[(pass == 1) ? 1 : 0];
            #pragma unroll
            for (int ks = 0; ks < 4; ks++) {
                uint32_t af[4][4];
                #pragma unroll
                for (int mi = 0; mi < 4; mi++) {
                    int row = warp_m + mi * 16 + ((g & 1) << 3) + lr;
                    int cb  = ks * 32 + ((g >> 1) << 4);
                    ldsm4(af[mi][0], af[mi][1], af[mi][2], af[mi][3],
                          swz_addr(abase, row, cb));
                }
                uint32_t bf[4][2];
                #pragma unroll
                for (int p = 0; p < 2; p++) {
                    int n  = warp_n + p * 16 + ((g >> 1) << 3) + lr;
                    int cb = ks * 32 + ((g & 1) << 4);
                    uint32_t r0, r1, r2, r3;
                    ldsm4(r0, r1, r2, r3, swz_addr(bbase, n, cb));
                    bf[p * 2 + 0][0] = r0; bf[p * 2 + 0][1] = r1;
                    bf[p * 2 + 1][0] = r2; bf[p * 2 + 1][1] = r3;
                }
                #pragma unroll
                for (int mi = 0; mi < 4; mi++)
                    #pragma unroll
                    for (int nj = 0; nj < 4; nj++)
                        mma16816(acc[mi][nj], af[mi], bf[nj][0], bf[nj][1]);
            }
        }
        __syncthreads();
    }

    int erow = lane >> 2;
    int ecol = (lane & 3) * 2;
    #pragma unroll
    for (int mi = 0; mi < 4; mi++) {
        #pragma unroll
        for (int nj = 0; nj < 4; nj++) {
            #pragma unroll
            for (int half = 0; half < 2; half++) {
                int r = row0 + warp_m + mi * 16 + erow + half * 8;
                #pragma unroll
                for (int rg = 0; rg < 2; rg++) {
                    int cp = col0 + warp_n + nj * 8 + ecol + rg;
                    if (MODE == 0) {
                        int h = cp >> 5, e = cp & 31;
                        float v = acc[mi][nj][half * 2 + rg] + bias[h * 96 + e * 3 + 2];
                        g_vh[(h * NM + r) * EE + e] = __float2half(v);
                    } else {
                        float v = acc[mi][nj][half * 2 + rg] + bias[cp];
                        out[r * DIMM + cp] = v;
                    }
                }
            }
        }
    }
}

// ---------------- k3: per-ball key means -> 3-way bf16 splits ------------------------
__global__ void k3_kmean() {
    int t = blockIdx.x * blockDim.x + threadIdx.x;
    int e = t & 31;
    int ball = (t >> 5) & (NB - 1);
    int h = t >> 14;
    const float* base = g_k + (h * NM + ball * MB) * EE + e;
    float s = 0.f;
    #pragma unroll
    for (int m = 0; m < MB; m++) s += base[m * EE];
    float v = s * (1.f / MB);
    __nv_bfloat16 b1 = __float2bfloat16(v);
    float f1 = __bfloat162float(b1);
    __nv_bfloat16 b2 = __float2bfloat16(v - f1);
    float f2 = __bfloat162float(b2);
    __nv_bfloat16 b3 = __float2bfloat16(v - f1 - f2);
    g_km1[t] = b1; g_km2[t] = b2; g_km3[t] = b3;
}

// ---------------- k4: sim via HMMA, 32 tok/warp, 4 chains, B prefetch ---------------
__device__ __forceinline__ void k4_load_b(uint32_t bfr[3][2][2], int h, int ball0,
                                          int mrow, int ep) {
    const __nv_bfloat16* ms[3] = {g_km1, g_km2, g_km3};
    #pragma unroll
    for (int s = 0; s < 3; s++) {
        const __nv_bfloat16* m = ms[s] + (h * NB + ball0 + mrow) * EE;
        #pragma unroll
        for (int kk = 0; kk < 2; kk++) {
            int e = kk * 16 + ep;
            bfr[s][kk][0] = *(const uint32_t*)(m + e);
            bfr[s][kk][1] = *(const uint32_t*)(m + e + 8);
        }
    }
}

__device__ __forceinline__ void top2_merge(float& v1, float& v2, int& i1, int& i2,
                                           float s, int c) {
    if (s > v1) { v2 = v1; i2 = i1; v1 = s; i1 = c; }
    else if (s > v2) { v2 = s; i2 = c; }
}

__global__ void __launch_bounds__(256, 2)
k4_top2() {
    int h = blockIdx.y;
    int tid = threadIdx.x;
    int wid = tid >> 5, lane = tid & 31;
    int tokw = blockIdx.x * 256 + wid * 32;   // 32 tokens per warp (2 m16 tiles)
    int mrow = lane >> 2;
    int ep   = (lane & 3) * 2;

    const __nv_bfloat16* qs[3] = {g_q1, g_q2, g_q3};

    uint32_t afr[2][3][2][4];   // [mtile][split][kstep][reg]
    #pragma unroll
    for (int m = 0; m < 2; m++) {
        #pragma unroll
        for (int s = 0; s < 3; s++) {
            const __nv_bfloat16* q = qs[s] + (h * NM + tokw + m * 16) * EE;
            #pragma unroll
            for (int kk = 0; kk < 2; kk++) {
                int e = kk * 16 + ep;
                afr[m][s][kk][0] = *(const uint32_t*)(q + (mrow    ) * EE + e);
                afr[m][s][kk][1] = *(const uint32_t*)(q + (mrow + 8) * EE + e);
                afr[m][s][kk][2] = *(const uint32_t*)(q + (mrow    ) * EE + e + 8);
                afr[m][s][kk][3] = *(const uint32_t*)(q + (mrow + 8) * EE + e + 8);
            }
        }
    }

    // top-2 state for 4 rows: idx = mtile*2 + half (half0: mrow, half1: mrow+8)
    float v1[4], v2[4];
    int   i1[4], i2[4];
    #pragma unroll
    for (int r = 0; r < 4; r++) { v1[r] = -1e30f; v2[r] = -1e30f; i1[r] = 0; i2[r] = 0; }

    uint32_t bf[2][3][2][2];
    k4_load_b(bf[0], h, 0, mrow, ep);

    #pragma unroll 2
    for (int grp = 0; grp < 64; grp++) {
        int cur = grp & 1;
        int ball0 = grp * 8;
        if (grp < 63)
            k4_load_b(bf[cur ^ 1], h, ball0 + 8, mrow, ep);

        // 4 independent chains: [mtile*2 + parity]
        float ac[4][4] = {};
        #pragma unroll
        for (int kk = 0; kk < 2; kk++) {
            uint32_t b00 = bf[cur][0][kk][0], b01 = bf[cur][0][kk][1];
            uint32_t b10 = bf[cur][1][kk][0], b11 = bf[cur][1][kk][1];
            uint32_t b20 = bf[cur][2][kk][0], b21 = bf[cur][2][kk][1];
            mma16816(ac[0], afr[0][0][kk], b00, b01);  // m0: 11
            mma16816(ac[2], afr[1][0][kk], b00, b01);  // m1: 11
            mma16816(ac[1], afr[0][0][kk], b10, b11);  // m0: 12
            mma16816(ac[3], afr[1][0][kk], b10, b11);  // m1: 12
            mma16816(ac[0], afr[0][1][kk], b00, b01);  // m0: 21
            mma16816(ac[2], afr[1][1][kk], b00, b01);  // m1: 21
            mma16816(ac[1], afr[0][1][kk], b10, b11);  // m0: 22
            mma16816(ac[3], afr[1][1][kk], b10, b11);  // m1: 22
            mma16816(ac[0], afr[0][0][kk], b20, b21);  // m0: 13
            mma16816(ac[2], afr[1][0][kk], b20, b21);  // m1: 13
            mma16816(ac[1], afr[0][2][kk], b00, b01);  // m0: 31
            mma16816(ac[3], afr[1][2][kk], b00, b01);  // m1: 31
        }

        int c0 = ball0 + ep, c1 = c0 + 1;
        #pragma unroll
        for (int m = 0; m < 2; m++) {
            float s0 = ac[2 * m][0] + ac[2 * m + 1][0];
            float s1 = ac[2 * m][1] + ac[2 * m + 1][1];
            float s2 = ac[2 * m][2] + ac[2 * m + 1][2];
            float s3 = ac[2 * m][3] + ac[2 * m + 1][3];
            int ra = m * 2, rb = m * 2 + 1;
            top2_merge(v1[ra], v2[ra], i1[ra], i2[ra], s0, c0);
            top2_merge(v1[ra], v2[ra], i1[ra], i2[ra], s1, c1);
            top2_merge(v1[rb], v2[rb], i1[rb], i2[rb], s2, c0);
            top2_merge(v1[rb], v2[rb], i1[rb], i2[rb], s3, c1);
        }
    }

    // merge top-2 across the 4 lanes of each row quad
    #pragma unroll
    for (int r = 0; r < 4; r++) {
        float a1 = v1[r], a2 = v2[r];
        int   b1 = i1[r], b2 = i2[r];
        #pragma unroll
        for (int d = 1; d < 4; d <<= 1) {
            float o1 = __shfl_xor_sync(0xffffffffu, a1, d);
            float o2 = __shfl_xor_sync(0xffffffffu, a2, d);
            int  oi1 = __shfl_xor_sync(0xffffffffu, b1, d);
            int  oi2 = __shfl_xor_sync(0xffffffffu, b2, d);
            if (o1 > a1) {
                if (a1 > o2) { a2 = a1; b2 = b1; } else { a2 = o2; b2 = oi2; }
                a1 = o1; b1 = oi1;
            } else if (o1 > a2) { a2 = o1; b2 = oi1; }
        }
        if ((lane & 3) == 0) {
            int tok = h * NM + tokw + (r >> 1) * 16 + (r & 1) * 8 + mrow;
            g_idx[tok * 2 + 0] = b1;
            g_idx[tok * 2 + 1] = b2;
        }
    }
}

// ---------------- k5: gathered 32-key attention (fp16 K,V) + bf16 split out ---------
__global__ void k5_attn() {
    int warp = (blockIdx.x * blockDim.x + threadIdx.x) >> 5;
    int lane = threadIdx.x & 31;
    int h = warp >> 13;
    int tok = warp & (NM - 1);
    int b0 = g_idx[warp * 2 + 0];
    int b1 = g_idx[warp * 2 + 1];

    int ball = (lane < 16) ? b0 : b1;
    int ktok = ball * MB + (lane & 15);
    const uint4*  kr4  = (const uint4*)(g_kh + (h * NM + ktok) * EE);
    const float4* qrow = (const float4*)(g_q + (h * NM + tok) * EE);
    float logit = 0.f;
    #pragma unroll
    for (int i = 0; i < 4; i++) {
        uint4 u = kr4[i];
        float4 qa = qrow[2 * i], qb = qrow[2 * i + 1];
        float2 k0 = __half22float2(*(__half2*)&u.x);
        float2 k1 = __half22float2(*(__half2*)&u.y);
        float2 k2 = __half22float2(*(__half2*)&u.z);
        float2 k3 = __half22float2(*(__half2*)&u.w);
        logit += qa.x * k0.x + qa.y * k0.y + qa.z * k1.x + qa.w * k1.y
               + qb.x * k2.x + qb.y * k2.y + qb.z * k3.x + qb.w * k3.y;
    }
    logit *= 0.17677669529663688f;

    float m = logit;
    #pragma unroll
    for (int off = 16; off > 0; off >>= 1)
        m = fmaxf(m, __shfl_xor_sync(0xffffffffu, m, off));
    float p = __expf(logit - m);
    float s = p;
    #pragma unroll
    for (int off = 16; off > 0; off >>= 1)
        s += __shfl_xor_sync(0xffffffffu, s, off);
    float attn = p / s;

    float out = 0.f;
    #pragma unroll
    for (int kk = 0; kk < NKEY; kk++) {
        float a = __shfl_sync(0xffffffffu, attn, kk);
        int kt = ((kk < 16) ? b0 : b1) * MB + (kk & 15);
        out += a * __half2float(g_vh[(h * NM + kt) * EE + lane]);
    }
    int oi = tok * DIMM + h * EE + lane;
    __nv_bfloat16 hi = __float2bfloat16(out);
    g_aoh[oi] = hi;
    g_aol[oi] = __float2bfloat16(out - __bfloat162float(hi));
}

// ---------------- launch --------------------------------------------------------------
extern "C" void kernel_launch(void* const* d_in, const int* in_sizes, int n_in,
                              void* d_out, int out_size) {
    const float* x     = (const float*)d_in[0];
    const float* pos   = (const float*)d_in[1];
    const float* Wqkv  = (const float*)d_in[2];
    const float* bqkv  = (const float*)d_in[3];
    const float* Wpe   = (const float*)d_in[4];
    const float* bpe   = (const float*)d_in[5];
    const float* Wproj = (const float*)d_in[6];
    const float* bproj = (const float*)d_in[7];
    float* out = (float*)d_out;

    const int DSMEM = 2 * 65536 + 1024;
    cudaFuncSetAttribute(gemm_mma<0>, cudaFuncAttributeMaxDynamicSharedMemorySize, DSMEM);
    cudaFuncSetAttribute(gemm_mma<1>, cudaFuncAttributeMaxDynamicSharedMemorySize, DSMEM);

    k01<<<1024 + NB, 256>>>(x, pos, Wpe, bpe, Wqkv, Wproj);
    k2_qk<<<dim3(NM / 128, 512 / 128), 256>>>(bqkv);
    gemm_mma<0><<<dim3(NM / 128, 256 / 128), 256, DSMEM>>>(bqkv, nullptr);
    k3_kmean<<<(NH * NB * EE) / 256, 256>>>();
    k4_top2<<<dim3(NM / 256, NH), 256>>>();
    k5_attn<<<(NH * NM * 32) / 256, 256>>>();
    gemm_mma<1><<<dim3(NM / 128, DIMM / 128), 256, DSMEM>>>(bproj, out);
}